// round 7
// baseline (speedup 1.0000x reference)
#include <cuda_runtime.h>
#include <math.h>

#define NB    8
#define TT    2048
#define BT    (NB*TT)      // 16384 rows
#define DM    256
#define DI    512
#define EPS   1e-5f
#define CHK   32           // chunks per sequence
#define CLEN  64           // steps per chunk (CHK*CLEN = TT)
#define NWRP  (NB*(DI/2)*CHK)   // 65536 scan warps

// ---------------- scratch (device globals: no allocation allowed) ----------------
__device__ float g_h[BT*DM];        // residual stream
__device__ float g_u[BT*DM];        // rmsnorm output
__device__ float g_xz[BT*2*DI];     // in_proj output (xi | z)
__device__ float g_xc[BT*DI];       // conv+silu output
__device__ float g_zs[BT*DI];       // silu(z)
__device__ float g_dbc[BT*48];      // x_proj output (dt_in | B | C)
__device__ float g_delta[BT*DI];    // softplus(dt)
__device__ float g_y[BT*DI];        // scan output (post gate)
__device__ float g_past[BT];        // past_soc
__device__ float g_P[NWRP*32];      // chunk decay products
__device__ float g_S[NWRP*32];      // chunk local sums
__device__ float g_Hi[NWRP*32];     // chunk initial states

// ---------------- helpers ----------------
__device__ __forceinline__ float warpSum(float v) {
    #pragma unroll
    for (int o = 16; o; o >>= 1) v += __shfl_xor_sync(0xffffffffu, v, o);
    return v;
}

__device__ __forceinline__ float siluf(float x) {
    return x / (1.f + __expf(-x));
}

// ---------------- kernel 0: launch-slot filler for ncu targeting -----------------
__global__ void k_warm() {}

// ------- kernel 1: input proj + layernorm + past_soc + rmsnorm (layer 0) --------
// warp per row; lane handles m = lane*8 .. lane*8+7.
__global__ __launch_bounds__(256) void k_embed(
    const float* __restrict__ x, const float* __restrict__ ipw,
    const float* __restrict__ ipb, const float* __restrict__ lng,
    const float* __restrict__ lnb, const float* __restrict__ rw)
{
    int w = threadIdx.x >> 5, lane = threadIdx.x & 31;
    int row = blockIdx.x*8 + w;
    int m0 = lane*8;
    const float* xr = x + (size_t)row*10;
    float xv[10];
    #pragma unroll
    for (int i = 0; i < 10; i++) xv[i] = __ldg(xr + i);

    float s[8]; float sum = 0.f;
    #pragma unroll
    for (int i = 0; i < 8; i++) {
        int m = m0 + i;
        float acc = ipb[m];
        #pragma unroll
        for (int j = 0; j < 10; j++) acc += xv[j]*__ldg(&ipw[m*10 + j]);
        s[i] = acc; sum += acc;
    }
    float mean = warpSum(sum) * (1.f/256.f);
    float vs = 0.f;
    #pragma unroll
    for (int i = 0; i < 8; i++) { s[i] -= mean; vs += s[i]*s[i]; }
    float inv = rsqrtf(warpSum(vs) * (1.f/256.f) + EPS);

    float hv[8]; float ss = 0.f;
    #pragma unroll
    for (int i = 0; i < 8; i++) {
        int m = m0 + i;
        hv[i] = s[i]*inv*lng[m] + lnb[m];
        ss += hv[i]*hv[i];
    }
    float* hp = g_h + (size_t)row*DM + m0;
    *(float4*)(hp)   = make_float4(hv[0],hv[1],hv[2],hv[3]);
    *(float4*)(hp+4) = make_float4(hv[4],hv[5],hv[6],hv[7]);

    float rinv = rsqrtf(warpSum(ss) * (1.f/256.f) + EPS);
    float uv[8];
    #pragma unroll
    for (int i = 0; i < 8; i++) uv[i] = hv[i]*rinv*rw[m0+i];
    float* up = g_u + (size_t)row*DM + m0;
    *(float4*)(up)   = make_float4(uv[0],uv[1],uv[2],uv[3]);
    *(float4*)(up+4) = make_float4(uv[4],uv[5],uv[6],uv[7]);

    if (lane == 0) g_past[row] = xv[9];
}

// ---------------- kernel 2: rmsnorm of residual stream -> g_u --------------------
__global__ __launch_bounds__(256) void k_rms(const float* __restrict__ wt) {
    int w = threadIdx.x >> 5, lane = threadIdx.x & 31;
    int row = blockIdx.x*8 + w;
    int m0 = lane*8;
    const float* hp = g_h + (size_t)row*DM + m0;
    float4 a = *(const float4*)(hp);
    float4 b = *(const float4*)(hp+4);
    float ss = a.x*a.x + a.y*a.y + a.z*a.z + a.w*a.w
             + b.x*b.x + b.y*b.y + b.z*b.z + b.w*b.w;
    float inv = rsqrtf(warpSum(ss) * (1.f/256.f) + EPS);
    float4 w0 = *(const float4*)(wt + m0);
    float4 w1 = *(const float4*)(wt + m0 + 4);
    float* up = g_u + (size_t)row*DM + m0;
    *(float4*)(up)   = make_float4(a.x*inv*w0.x, a.y*inv*w0.y, a.z*inv*w0.z, a.w*inv*w0.w);
    *(float4*)(up+4) = make_float4(b.x*inv*w1.x, b.y*inv*w1.y, b.z*inv*w1.z, b.w*inv*w1.w);
}

// ---------------- kernel 3: NT SGEMM, 128x128x8, double-buffered -----------------
// smem rows padded to 132 -> conflict-free staging stores.
template<int EPI>
__global__ __launch_bounds__(256, 2) void k_sgemm_nt(
    const float* __restrict__ A, const float* __restrict__ Bm,
    float* __restrict__ C, int M, int N, int K)
{
    __shared__ float As[2][8][132];
    __shared__ float Bs[2][8][132];
    int tid = threadIdx.x;
    int mBase = blockIdx.y * 128, nBase = blockIdx.x * 128;

    int lr = tid >> 1;
    int lk = (tid & 1) * 4;
    const float* Ag = A + (size_t)(mBase + lr)*K + lk;
    const float* Bg = Bm + (size_t)(nBase + lr)*K + lk;

    int warp = tid >> 5, lane = tid & 31;
    int wm = warp & 1, wn = warp >> 1;
    int tm = lane & 7, tn = lane >> 3;
    int aoff = wm*64 + tm*4;
    int boff = wn*32 + tn*4;

    float acc[8][8];
    #pragma unroll
    for (int i = 0; i < 8; i++)
        #pragma unroll
        for (int j = 0; j < 8; j++) acc[i][j] = 0.f;

    float4 pa = *(const float4*)Ag;
    float4 pb = *(const float4*)Bg;
    As[0][lk+0][lr] = pa.x; As[0][lk+1][lr] = pa.y;
    As[0][lk+2][lr] = pa.z; As[0][lk+3][lr] = pa.w;
    Bs[0][lk+0][lr] = pb.x; Bs[0][lk+1][lr] = pb.y;
    Bs[0][lk+2][lr] = pb.z; Bs[0][lk+3][lr] = pb.w;
    __syncthreads();

    int buf = 0;
    for (int kb = 8; kb <= K; kb += 8) {
        if (kb < K) {
            pa = *(const float4*)(Ag + kb);
            pb = *(const float4*)(Bg + kb);
        }
        #pragma unroll
        for (int k = 0; k < 8; k++) {
            float a[8], b[8];
            *(float4*)(a)   = *(const float4*)&As[buf][k][aoff];
            *(float4*)(a+4) = *(const float4*)&As[buf][k][aoff+32];
            *(float4*)(b)   = *(const float4*)&Bs[buf][k][boff];
            *(float4*)(b+4) = *(const float4*)&Bs[buf][k][boff+16];
            #pragma unroll
            for (int i = 0; i < 8; i++)
                #pragma unroll
                for (int j = 0; j < 8; j++) acc[i][j] += a[i]*b[j];
        }
        if (kb < K) {
            buf ^= 1;
            As[buf][lk+0][lr] = pa.x; As[buf][lk+1][lr] = pa.y;
            As[buf][lk+2][lr] = pa.z; As[buf][lk+3][lr] = pa.w;
            Bs[buf][lk+0][lr] = pb.x; Bs[buf][lk+1][lr] = pb.y;
            Bs[buf][lk+2][lr] = pb.z; Bs[buf][lk+3][lr] = pb.w;
            __syncthreads();
        }
    }

    #pragma unroll
    for (int i = 0; i < 8; i++) {
        int mloc = wm*64 + ((i < 4) ? (tm*4 + i) : (32 + tm*4 + i - 4));
        float* Cp = C + (size_t)(mBase + mloc)*N + nBase;
        if (EPI == 0) {
            *(float4*)(Cp + boff)      = make_float4(acc[i][0],acc[i][1],acc[i][2],acc[i][3]);
            *(float4*)(Cp + boff + 16) = make_float4(acc[i][4],acc[i][5],acc[i][6],acc[i][7]);
        } else {
            float4 c0 = *(const float4*)(Cp + boff);
            float4 c1 = *(const float4*)(Cp + boff + 16);
            c0.x += acc[i][0]; c0.y += acc[i][1]; c0.z += acc[i][2]; c0.w += acc[i][3];
            c1.x += acc[i][4]; c1.y += acc[i][5]; c1.z += acc[i][6]; c1.w += acc[i][7];
            *(float4*)(Cp + boff)      = c0;
            *(float4*)(Cp + boff + 16) = c1;
        }
    }
}

// ------ kernel 4: FUSED conv+silu (+z-silu) + x_proj + dt_proj + softplus --------
__global__ __launch_bounds__(256) void k_convdbc(
    const float* __restrict__ cw, const float* __restrict__ cb,
    const float* __restrict__ xpw, const float* __restrict__ dtw,
    const float* __restrict__ dtb)
{
    __shared__ float xs[8][512];
    __shared__ float dbc_s[8][48];
    int r0 = blockIdx.x * 8;
    int tid = threadIdx.x;

    #pragma unroll
    for (int i = 0; i < 4; i++) {
        int item = i*256 + tid;
        int rg = item >> 9;
        int d = item & (DI-1);
        size_t row0 = (size_t)r0 + rg*4;
        int t0 = (int)(row0 & (TT-1));
        const float* w = cw + d*4;
        float w0 = w[0], w1 = w[1], w2 = w[2], w3 = w[3];
        float bias = cb[d];

        float xm3 = 0.f, xm2 = 0.f, xm1 = 0.f;
        if (t0 > 0) {
            xm3 = g_xz[(row0-3)*1024 + d];
            xm2 = g_xz[(row0-2)*1024 + d];
            xm1 = g_xz[(row0-1)*1024 + d];
        }
        float x0 = g_xz[(row0+0)*1024 + d];
        float x1 = g_xz[(row0+1)*1024 + d];
        float x2 = g_xz[(row0+2)*1024 + d];
        float x3 = g_xz[(row0+3)*1024 + d];

        float c0 = siluf(bias + w0*xm3 + w1*xm2 + w2*xm1 + w3*x0);
        float c1 = siluf(bias + w0*xm2 + w1*xm1 + w2*x0  + w3*x1);
        float c2 = siluf(bias + w0*xm1 + w1*x0  + w2*x1  + w3*x2);
        float c3 = siluf(bias + w0*x0  + w1*x1  + w2*x2  + w3*x3);
        int lr = rg*4;
        xs[lr+0][d] = c0; xs[lr+1][d] = c1; xs[lr+2][d] = c2; xs[lr+3][d] = c3;
        g_xc[(row0+0)*512 + d] = c0;
        g_xc[(row0+1)*512 + d] = c1;
        g_xc[(row0+2)*512 + d] = c2;
        g_xc[(row0+3)*512 + d] = c3;
        #pragma unroll
        for (int j = 0; j < 4; j++) {
            float z = g_xz[(row0+j)*1024 + 512 + d];
            g_zs[(row0+j)*512 + d] = siluf(z);
        }
    }
    __syncthreads();

    int w = tid >> 5, lane = tid & 31;
    const float4* xr = (const float4*)xs[w];
    const float4* wp = (const float4*)xpw;
    for (int e = 0; e < 48; e++) {
        float s = 0.f;
        #pragma unroll
        for (int i = 0; i < 4; i++) {
            float4 xv = xr[lane + 32*i];
            float4 wv = __ldg(&wp[e*128 + lane + 32*i]);
            s += xv.x*wv.x + xv.y*wv.y + xv.z*wv.z + xv.w*wv.w;
        }
        #pragma unroll
        for (int o = 16; o; o >>= 1) s += __shfl_xor_sync(0xffffffffu, s, o);
        if (lane == 0) {
            dbc_s[w][e] = s;
            g_dbc[(size_t)(r0 + w)*48 + e] = s;
        }
    }
    __syncthreads();

    #pragma unroll
    for (int i = 0; i < 16; i++) {
        int idx = i*256 + tid;
        int r = idx >> 9;
        int d = idx & (DI-1);
        const float4* wr = (const float4*)(dtw + d*16);
        const float4* dr = (const float4*)dbc_s[r];
        float acc = dtb[d];
        #pragma unroll
        for (int c = 0; c < 4; c++) {
            float4 dv = dr[c];
            float4 wv = __ldg(&wr[c]);
            acc += dv.x*wv.x + dv.y*wv.y + dv.z*wv.z + dv.w*wv.w;
        }
        g_delta[(size_t)(r0 + r)*512 + d] = (acc > 20.f) ? acc : log1pf(__expf(acc));
    }
}

// -------- kernel 5a: scan pass A — per-chunk (P = prod dA, S = local h) ----------
__global__ __launch_bounds__(256) void k_scanA(const float* __restrict__ A_log) {
    int gw = blockIdx.x*8 + (threadIdx.x >> 5);
    int lane = threadIdx.x & 31;
    int c = gw & (CHK-1);
    int dp = (gw >> 5) & 255;
    int b = gw >> 13;
    int half = lane >> 4, n = lane & 15;
    int d = dp*2 + half;
    float na = -__expf(A_log[d*16 + n]);
    size_t row = (size_t)b*TT + c*CLEN;
    const float* pdl = g_delta + row*512 + d;
    const float* pxi = g_xc    + row*512 + d;
    const float* pB  = g_dbc   + row*48 + 16 + n;
    float P = 1.f, S = 0.f;
    #pragma unroll 4
    for (int t = 0; t < CLEN; t++) {
        float dl = __ldg(pdl); pdl += 512;
        float xi = __ldg(pxi); pxi += 512;
        float Bv = __ldg(pB);  pB  += 48;
        float da = __expf(dl * na);
        P *= da;
        S = da*S + (dl*xi)*Bv;
    }
    size_t o = (size_t)gw*32 + lane;
    g_P[o] = P;
    g_S[o] = S;
}

// -------- kernel 5b: scan pass B — serial prefix over the 32 chunks --------------
__global__ __launch_bounds__(256) void k_scanB() {
    int t = blockIdx.x*256 + threadIdx.x;
    int lane = t & 31;
    int wdp = t >> 5;
    float h = 0.f;
    size_t o = (size_t)wdp*CHK*32 + lane;
    #pragma unroll
    for (int c = 0; c < CHK; c++, o += 32) {
        g_Hi[o] = h;
        h = g_P[o]*h + g_S[o];
    }
}

// -------- kernel 5c: scan pass C — re-run chunk from Hinit, emit outputs ---------
__global__ __launch_bounds__(256) void k_scanC(
    const float* __restrict__ A_log, const float* __restrict__ Dp)
{
    int gw = blockIdx.x*8 + (threadIdx.x >> 5);
    int lane = threadIdx.x & 31;
    int c = gw & (CHK-1);
    int dp = (gw >> 5) & 255;
    int b = gw >> 13;
    int half = lane >> 4, n = lane & 15;
    int d = dp*2 + half;
    float na = -__expf(A_log[d*16 + n]);
    float Dv = Dp[d];
    float h = g_Hi[(size_t)gw*32 + lane];
    size_t row = (size_t)b*TT + c*CLEN;
    const float* pdl = g_delta + row*512 + d;
    const float* pxi = g_xc    + row*512 + d;
    const float* pB  = g_dbc   + row*48 + 16 + n;
    const float* pC  = g_dbc   + row*48 + 32 + n;
    const float* pz  = g_zs    + row*512 + d;
    float*       py  = g_y     + row*512 + d;
    #pragma unroll 4
    for (int t = 0; t < CLEN; t++) {
        float dl = __ldg(pdl); pdl += 512;
        float xi = __ldg(pxi); pxi += 512;
        float Bv = __ldg(pB);  pB  += 48;
        float Cv = __ldg(pC);  pC  += 48;
        float da = __expf(dl * na);
        h = da*h + (dl*xi)*Bv;
        float v = h * Cv;
        #pragma unroll
        for (int o = 8; o; o >>= 1) v += __shfl_xor_sync(0xffffffffu, v, o);
        if (n == 0) {
            float y = v + Dv*xi;
            *py = y * __ldg(pz);
        }
        pz += 512; py += 512;
    }
}

// ---------------- kernel 6: final rmsnorm + head + output ----------------
__global__ __launch_bounds__(256) void k_final(
    const float* __restrict__ fw, const float* __restrict__ hw,
    const float* __restrict__ hb, float* __restrict__ out)
{
    int w = threadIdx.x >> 5, lane = threadIdx.x & 31;
    int row = blockIdx.x*8 + w;
    int m0 = lane*8;
    const float* hp = g_h + (size_t)row*DM + m0;
    float4 a = *(const float4*)(hp);
    float4 b = *(const float4*)(hp+4);
    float ss = a.x*a.x + a.y*a.y + a.z*a.z + a.w*a.w
             + b.x*b.x + b.y*b.y + b.z*b.z + b.w*b.w;
    float inv = rsqrtf(warpSum(ss) * (1.f/256.f) + EPS);
    float4 f0 = *(const float4*)(fw + m0);
    float4 f1 = *(const float4*)(fw + m0 + 4);
    float4 h0 = *(const float4*)(hw + m0);
    float4 h1 = *(const float4*)(hw + m0 + 4);
    float dot = a.x*inv*f0.x*h0.x + a.y*inv*f0.y*h0.y + a.z*inv*f0.z*h0.z + a.w*inv*f0.w*h0.w
              + b.x*inv*f1.x*h1.x + b.y*inv*f1.y*h1.y + b.z*inv*f1.z*h1.z + b.w*inv*f1.w*h1.w;
    dot = warpSum(dot);
    if (lane == 0) {
        float dlt = dot + hb[0];
        out[row] = g_past[row] + dlt;      // y
        out[BT + row] = dlt;               // delta
    }
}

// ---------------- host launcher ----------------
extern "C" void kernel_launch(void* const* d_in, const int* in_sizes, int n_in,
                              void* d_out, int out_size)
{
    const float* x    = (const float*)d_in[0];
    const float* ipw  = (const float*)d_in[1];
    const float* ipb  = (const float*)d_in[2];
    const float* lng  = (const float*)d_in[3];
    const float* lnb  = (const float*)d_in[4];
    const float* inpw = (const float*)d_in[5];   // (2,1024,256)
    const float* cw   = (const float*)d_in[6];   // (2,512,1,4)
    const float* cb   = (const float*)d_in[7];   // (2,512)
    const float* xpw  = (const float*)d_in[8];   // (2,48,512)
    const float* dtw  = (const float*)d_in[9];   // (2,512,16)
    const float* dtb  = (const float*)d_in[10];  // (2,512)
    const float* alog = (const float*)d_in[11];  // (2,512,16)
    const float* dpar = (const float*)d_in[12];  // (2,512)
    const float* opw  = (const float*)d_in[13];  // (2,256,512)
    const float* rmsw = (const float*)d_in[14];  // (2,256)
    const float* frw  = (const float*)d_in[15];  // (256)
    const float* hw   = (const float*)d_in[16];  // (1,256)
    const float* hb   = (const float*)d_in[17];  // (1)
    float* out = (float*)d_out;

    float *pu, *pxz, *py, *ph;
    cudaGetSymbolAddress((void**)&pu,  g_u);
    cudaGetSymbolAddress((void**)&pxz, g_xz);
    cudaGetSymbolAddress((void**)&py,  g_y);
    cudaGetSymbolAddress((void**)&ph,  g_h);

    // launch order: warm(1), embed(2), sgemm0(3), convdbc(4 = ncu capture slot)
    k_warm<<<1, 32>>>();
    k_embed<<<BT/8, 256>>>(x, ipw, ipb, lng, lnb, rmsw);   // includes layer-0 rmsnorm

    for (int l = 0; l < 2; l++) {
        if (l > 0) k_rms<<<BT/8, 256>>>(rmsw + l*DM);
        k_sgemm_nt<0><<<dim3(1024/128, BT/128), 256>>>(pu, inpw + (size_t)l*1024*256, pxz, BT, 1024, 256);
        k_convdbc<<<BT/8, 256>>>(cw + l*DI*4, cb + l*DI, xpw + l*48*512, dtw + l*DI*16, dtb + l*DI);
        k_scanA<<<NWRP/8, 256>>>(alog + l*DI*16);
        k_scanB<<<256, 256>>>();
        k_scanC<<<NWRP/8, 256>>>(alog + l*DI*16, dpar + l*DI);
        k_sgemm_nt<1><<<dim3(256/128, BT/128), 256>>>(py, opw + (size_t)l*256*512, ph, BT, 256, 512);
    }

    k_final<<<BT/8, 256>>>(frw, hw, hb, out);
}

// round 9
// speedup vs baseline: 1.0039x; 1.0039x over previous
#include <cuda_runtime.h>
#include <math.h>

#define NB    8
#define TT    2048
#define BT    (NB*TT)      // 16384 rows
#define DM    256
#define DI    512
#define EPS   1e-5f
#define CHK   32           // chunks per sequence
#define CLEN  64           // steps per chunk (CHK*CLEN = TT)
#define NWRP  (NB*(DI/2)*CHK)   // 65536 scan warps

// ---------------- scratch (device globals: no allocation allowed) ----------------
__device__ float g_h[BT*DM];        // residual stream
__device__ float g_u[BT*DM];        // rmsnorm output
__device__ float g_xz[BT*2*DI];     // in_proj output (xi | z)
__device__ float g_xc[BT*DI];       // conv+silu output
__device__ float g_zs[BT*DI];       // silu(z)
__device__ float g_dbc[BT*48];      // x_proj output (dt_in | B | C)
__device__ float g_delta[BT*DI];    // softplus(dt)
__device__ float g_y[BT*DI];        // scan output (post gate)
__device__ float g_past[BT];        // past_soc
__device__ float g_P[NWRP*32];      // chunk decay products
__device__ float g_S[NWRP*32];      // chunk local sums
__device__ float g_Hi[NWRP*32];     // chunk initial states

// ---------------- helpers ----------------
__device__ __forceinline__ float warpSum(float v) {
    #pragma unroll
    for (int o = 16; o; o >>= 1) v += __shfl_xor_sync(0xffffffffu, v, o);
    return v;
}

__device__ __forceinline__ float siluf(float x) {
    return x / (1.f + __expf(-x));
}

// ---------------- kernel 0: launch-slot filler for ncu targeting -----------------
__global__ void k_warm() {}

// ------- kernel 1: input proj + layernorm + past_soc + rmsnorm (layer 0) --------
__global__ __launch_bounds__(256) void k_embed(
    const float* __restrict__ x, const float* __restrict__ ipw,
    const float* __restrict__ ipb, const float* __restrict__ lng,
    const float* __restrict__ lnb, const float* __restrict__ rw)
{
    int w = threadIdx.x >> 5, lane = threadIdx.x & 31;
    int row = blockIdx.x*8 + w;
    int m0 = lane*8;
    const float* xr = x + (size_t)row*10;
    float xv[10];
    #pragma unroll
    for (int i = 0; i < 10; i++) xv[i] = __ldg(xr + i);

    float s[8]; float sum = 0.f;
    #pragma unroll
    for (int i = 0; i < 8; i++) {
        int m = m0 + i;
        float acc = ipb[m];
        #pragma unroll
        for (int j = 0; j < 10; j++) acc += xv[j]*__ldg(&ipw[m*10 + j]);
        s[i] = acc; sum += acc;
    }
    float mean = warpSum(sum) * (1.f/256.f);
    float vs = 0.f;
    #pragma unroll
    for (int i = 0; i < 8; i++) { s[i] -= mean; vs += s[i]*s[i]; }
    float inv = rsqrtf(warpSum(vs) * (1.f/256.f) + EPS);

    float hv[8]; float ss = 0.f;
    #pragma unroll
    for (int i = 0; i < 8; i++) {
        int m = m0 + i;
        hv[i] = s[i]*inv*lng[m] + lnb[m];
        ss += hv[i]*hv[i];
    }
    float* hp = g_h + (size_t)row*DM + m0;
    *(float4*)(hp)   = make_float4(hv[0],hv[1],hv[2],hv[3]);
    *(float4*)(hp+4) = make_float4(hv[4],hv[5],hv[6],hv[7]);

    float rinv = rsqrtf(warpSum(ss) * (1.f/256.f) + EPS);
    float uv[8];
    #pragma unroll
    for (int i = 0; i < 8; i++) uv[i] = hv[i]*rinv*rw[m0+i];
    float* up = g_u + (size_t)row*DM + m0;
    *(float4*)(up)   = make_float4(uv[0],uv[1],uv[2],uv[3]);
    *(float4*)(up+4) = make_float4(uv[4],uv[5],uv[6],uv[7]);

    if (lane == 0) g_past[row] = xv[9];
}

// ---------------- kernel 2: rmsnorm of residual stream -> g_u --------------------
__global__ __launch_bounds__(256) void k_rms(const float* __restrict__ wt) {
    int w = threadIdx.x >> 5, lane = threadIdx.x & 31;
    int row = blockIdx.x*8 + w;
    int m0 = lane*8;
    const float* hp = g_h + (size_t)row*DM + m0;
    float4 a = *(const float4*)(hp);
    float4 b = *(const float4*)(hp+4);
    float ss = a.x*a.x + a.y*a.y + a.z*a.z + a.w*a.w
             + b.x*b.x + b.y*b.y + b.z*b.z + b.w*b.w;
    float inv = rsqrtf(warpSum(ss) * (1.f/256.f) + EPS);
    float4 w0 = *(const float4*)(wt + m0);
    float4 w1 = *(const float4*)(wt + m0 + 4);
    float* up = g_u + (size_t)row*DM + m0;
    *(float4*)(up)   = make_float4(a.x*inv*w0.x, a.y*inv*w0.y, a.z*inv*w0.z, a.w*inv*w0.w);
    *(float4*)(up+4) = make_float4(b.x*inv*w1.x, b.y*inv*w1.y, b.z*inv*w1.z, b.w*inv*w1.w);
}

// ---------------- kernel 3: NT SGEMM, 128x128x8, double-buffered -----------------
// (round-4/6 version, measured 193.8us — padding experiment reverted)
template<int EPI>
__global__ __launch_bounds__(256) void k_sgemm_nt(
    const float* __restrict__ A, const float* __restrict__ Bm,
    float* __restrict__ C, int M, int N, int K)
{
    __shared__ float As[2][8][128];
    __shared__ float Bs[2][8][128];
    int tid = threadIdx.x;
    int mBase = blockIdx.y * 128, nBase = blockIdx.x * 128;

    int lr = tid >> 1;
    int lk = (tid & 1) * 4;
    const float* Ag = A + (size_t)(mBase + lr)*K + lk;
    const float* Bg = Bm + (size_t)(nBase + lr)*K + lk;

    int warp = tid >> 5, lane = tid & 31;
    int wm = warp & 1, wn = warp >> 1;
    int tm = lane & 7, tn = lane >> 3;
    int aoff = wm*64 + tm*4;
    int boff = wn*32 + tn*4;

    float acc[8][8];
    #pragma unroll
    for (int i = 0; i < 8; i++)
        #pragma unroll
        for (int j = 0; j < 8; j++) acc[i][j] = 0.f;

    float4 pa = *(const float4*)Ag;
    float4 pb = *(const float4*)Bg;
    As[0][lk+0][lr] = pa.x; As[0][lk+1][lr] = pa.y;
    As[0][lk+2][lr] = pa.z; As[0][lk+3][lr] = pa.w;
    Bs[0][lk+0][lr] = pb.x; Bs[0][lk+1][lr] = pb.y;
    Bs[0][lk+2][lr] = pb.z; Bs[0][lk+3][lr] = pb.w;
    __syncthreads();

    int buf = 0;
    for (int kb = 8; kb <= K; kb += 8) {
        if (kb < K) {
            pa = *(const float4*)(Ag + kb);
            pb = *(const float4*)(Bg + kb);
        }
        #pragma unroll
        for (int k = 0; k < 8; k++) {
            float a[8], b[8];
            *(float4*)(a)   = *(const float4*)&As[buf][k][aoff];
            *(float4*)(a+4) = *(const float4*)&As[buf][k][aoff+32];
            *(float4*)(b)   = *(const float4*)&Bs[buf][k][boff];
            *(float4*)(b+4) = *(const float4*)&Bs[buf][k][boff+16];
            #pragma unroll
            for (int i = 0; i < 8; i++)
                #pragma unroll
                for (int j = 0; j < 8; j++) acc[i][j] += a[i]*b[j];
        }
        if (kb < K) {
            buf ^= 1;
            As[buf][lk+0][lr] = pa.x; As[buf][lk+1][lr] = pa.y;
            As[buf][lk+2][lr] = pa.z; As[buf][lk+3][lr] = pa.w;
            Bs[buf][lk+0][lr] = pb.x; Bs[buf][lk+1][lr] = pb.y;
            Bs[buf][lk+2][lr] = pb.z; Bs[buf][lk+3][lr] = pb.w;
            __syncthreads();
        }
    }

    #pragma unroll
    for (int i = 0; i < 8; i++) {
        int mloc = wm*64 + ((i < 4) ? (tm*4 + i) : (32 + tm*4 + i - 4));
        float* Cp = C + (size_t)(mBase + mloc)*N + nBase;
        if (EPI == 0) {
            *(float4*)(Cp + boff)      = make_float4(acc[i][0],acc[i][1],acc[i][2],acc[i][3]);
            *(float4*)(Cp + boff + 16) = make_float4(acc[i][4],acc[i][5],acc[i][6],acc[i][7]);
        } else {
            float4 c0 = *(const float4*)(Cp + boff);
            float4 c1 = *(const float4*)(Cp + boff + 16);
            c0.x += acc[i][0]; c0.y += acc[i][1]; c0.z += acc[i][2]; c0.w += acc[i][3];
            c1.x += acc[i][4]; c1.y += acc[i][5]; c1.z += acc[i][6]; c1.w += acc[i][7];
            *(float4*)(Cp + boff)      = c0;
            *(float4*)(Cp + boff + 16) = c1;
        }
    }
}

// ------ kernel 4: FUSED conv+silu (+z-silu) + x_proj + dt_proj + softplus --------
// x_proj phase is e-major: warp w computes e in [6w, 6w+6) for all 8 rows,
// weights register-resident -> 8x fewer xpw LDG.128.
__global__ __launch_bounds__(256) void k_convdbc(
    const float* __restrict__ cw, const float* __restrict__ cb,
    const float* __restrict__ xpw, const float* __restrict__ dtw,
    const float* __restrict__ dtb)
{
    __shared__ float xs[8][512];
    __shared__ float dbc_s[8][48];
    int r0 = blockIdx.x * 8;
    int tid = threadIdx.x;

    #pragma unroll
    for (int i = 0; i < 4; i++) {
        int item = i*256 + tid;
        int rg = item >> 9;
        int d = item & (DI-1);
        size_t row0 = (size_t)r0 + rg*4;
        int t0 = (int)(row0 & (TT-1));
        const float* w = cw + d*4;
        float w0 = w[0], w1 = w[1], w2 = w[2], w3 = w[3];
        float bias = cb[d];

        float xm3 = 0.f, xm2 = 0.f, xm1 = 0.f;
        if (t0 > 0) {
            xm3 = g_xz[(row0-3)*1024 + d];
            xm2 = g_xz[(row0-2)*1024 + d];
            xm1 = g_xz[(row0-1)*1024 + d];
        }
        float x0 = g_xz[(row0+0)*1024 + d];
        float x1 = g_xz[(row0+1)*1024 + d];
        float x2 = g_xz[(row0+2)*1024 + d];
        float x3 = g_xz[(row0+3)*1024 + d];

        float c0 = siluf(bias + w0*xm3 + w1*xm2 + w2*xm1 + w3*x0);
        float c1 = siluf(bias + w0*xm2 + w1*xm1 + w2*x0  + w3*x1);
        float c2 = siluf(bias + w0*xm1 + w1*x0  + w2*x1  + w3*x2);
        float c3 = siluf(bias + w0*x0  + w1*x1  + w2*x2  + w3*x3);
        int lr = rg*4;
        xs[lr+0][d] = c0; xs[lr+1][d] = c1; xs[lr+2][d] = c2; xs[lr+3][d] = c3;
        g_xc[(row0+0)*512 + d] = c0;
        g_xc[(row0+1)*512 + d] = c1;
        g_xc[(row0+2)*512 + d] = c2;
        g_xc[(row0+3)*512 + d] = c3;
        #pragma unroll
        for (int j = 0; j < 4; j++) {
            float z = g_xz[(row0+j)*1024 + 512 + d];
            g_zs[(row0+j)*512 + d] = siluf(z);
        }
    }
    __syncthreads();

    // x_proj phase (e-major, weights in registers)
    int w = tid >> 5, lane = tid & 31;
    const float4* wp = (const float4*)xpw;
    #pragma unroll
    for (int e0 = 0; e0 < 6; e0++) {
        int e = w*6 + e0;
        float4 wv0 = __ldg(&wp[e*128 + lane]);
        float4 wv1 = __ldg(&wp[e*128 + lane + 32]);
        float4 wv2 = __ldg(&wp[e*128 + lane + 64]);
        float4 wv3 = __ldg(&wp[e*128 + lane + 96]);
        #pragma unroll
        for (int r = 0; r < 8; r++) {
            const float4* xr = (const float4*)xs[r];
            float4 x0 = xr[lane], x1 = xr[lane+32], x2 = xr[lane+64], x3 = xr[lane+96];
            float s = x0.x*wv0.x + x0.y*wv0.y + x0.z*wv0.z + x0.w*wv0.w
                    + x1.x*wv1.x + x1.y*wv1.y + x1.z*wv1.z + x1.w*wv1.w
                    + x2.x*wv2.x + x2.y*wv2.y + x2.z*wv2.z + x2.w*wv2.w
                    + x3.x*wv3.x + x3.y*wv3.y + x3.z*wv3.z + x3.w*wv3.w;
            #pragma unroll
            for (int o = 16; o; o >>= 1) s += __shfl_xor_sync(0xffffffffu, s, o);
            if (lane == 0) {
                dbc_s[r][e] = s;
                g_dbc[(size_t)(r0 + r)*48 + e] = s;
            }
        }
    }
    __syncthreads();

    // dt_proj + softplus phase
    #pragma unroll
    for (int i = 0; i < 16; i++) {
        int idx = i*256 + tid;
        int r = idx >> 9;
        int d = idx & (DI-1);
        const float4* wr = (const float4*)(dtw + d*16);
        const float4* dr = (const float4*)dbc_s[r];
        float acc = dtb[d];
        #pragma unroll
        for (int c = 0; c < 4; c++) {
            float4 dv = dr[c];
            float4 wv = __ldg(&wr[c]);
            acc += dv.x*wv.x + dv.y*wv.y + dv.z*wv.z + dv.w*wv.w;
        }
        g_delta[(size_t)(r0 + r)*512 + d] = (acc > 20.f) ? acc : log1pf(__expf(acc));
    }
}

// -------- kernel 5a: scan pass A — per-chunk (P = prod dA, S = local h) ----------
__global__ __launch_bounds__(256) void k_scanA(const float* __restrict__ A_log) {
    int gw = blockIdx.x*8 + (threadIdx.x >> 5);
    int lane = threadIdx.x & 31;
    int c = gw & (CHK-1);
    int dp = (gw >> 5) & 255;
    int b = gw >> 13;
    int half = lane >> 4, n = lane & 15;
    int d = dp*2 + half;
    float na = -__expf(A_log[d*16 + n]);
    size_t row = (size_t)b*TT + c*CLEN;
    const float* pdl = g_delta + row*512 + d;
    const float* pxi = g_xc    + row*512 + d;
    const float* pB  = g_dbc   + row*48 + 16 + n;
    float P = 1.f, S = 0.f;
    #pragma unroll 4
    for (int t = 0; t < CLEN; t++) {
        float dl = __ldg(pdl); pdl += 512;
        float xi = __ldg(pxi); pxi += 512;
        float Bv = __ldg(pB);  pB  += 48;
        float da = __expf(dl * na);
        P *= da;
        S = da*S + (dl*xi)*Bv;
    }
    size_t o = (size_t)gw*32 + lane;
    g_P[o] = P;
    g_S[o] = S;
}

// -------- kernel 5b: scan pass B — serial prefix over the 32 chunks --------------
__global__ __launch_bounds__(256) void k_scanB() {
    int t = blockIdx.x*256 + threadIdx.x;
    int lane = t & 31;
    int wdp = t >> 5;
    float h = 0.f;
    size_t o = (size_t)wdp*CHK*32 + lane;
    #pragma unroll
    for (int c = 0; c < CHK; c++, o += 32) {
        g_Hi[o] = h;
        h = g_P[o]*h + g_S[o];
    }
}

// -------- kernel 5c: scan pass C — re-run chunk from Hinit, emit outputs ---------
__global__ __launch_bounds__(256) void k_scanC(
    const float* __restrict__ A_log, const float* __restrict__ Dp)
{
    int gw = blockIdx.x*8 + (threadIdx.x >> 5);
    int lane = threadIdx.x & 31;
    int c = gw & (CHK-1);
    int dp = (gw >> 5) & 255;
    int b = gw >> 13;
    int half = lane >> 4, n = lane & 15;
    int d = dp*2 + half;
    float na = -__expf(A_log[d*16 + n]);
    float Dv = Dp[d];
    float h = g_Hi[(size_t)gw*32 + lane];
    size_t row = (size_t)b*TT + c*CLEN;
    const float* pdl = g_delta + row*512 + d;
    const float* pxi = g_xc    + row*512 + d;
    const float* pB  = g_dbc   + row*48 + 16 + n;
    const float* pC  = g_dbc   + row*48 + 32 + n;
    const float* pz  = g_zs    + row*512 + d;
    float*       py  = g_y     + row*512 + d;
    #pragma unroll 4
    for (int t = 0; t < CLEN; t++) {
        float dl = __ldg(pdl); pdl += 512;
        float xi = __ldg(pxi); pxi += 512;
        float Bv = __ldg(pB);  pB  += 48;
        float Cv = __ldg(pC);  pC  += 48;
        float da = __expf(dl * na);
        h = da*h + (dl*xi)*Bv;
        float v = h * Cv;
        #pragma unroll
        for (int o = 8; o; o >>= 1) v += __shfl_xor_sync(0xffffffffu, v, o);
        if (n == 0) {
            float y = v + Dv*xi;
            *py = y * __ldg(pz);
        }
        pz += 512; py += 512;
    }
}

// ---------------- kernel 6: final rmsnorm + head + output ----------------
__global__ __launch_bounds__(256) void k_final(
    const float* __restrict__ fw, const float* __restrict__ hw,
    const float* __restrict__ hb, float* __restrict__ out)
{
    int w = threadIdx.x >> 5, lane = threadIdx.x & 31;
    int row = blockIdx.x*8 + w;
    int m0 = lane*8;
    const float* hp = g_h + (size_t)row*DM + m0;
    float4 a = *(const float4*)(hp);
    float4 b = *(const float4*)(hp+4);
    float ss = a.x*a.x + a.y*a.y + a.z*a.z + a.w*a.w
             + b.x*b.x + b.y*b.y + b.z*b.z + b.w*b.w;
    float inv = rsqrtf(warpSum(ss) * (1.f/256.f) + EPS);
    float4 f0 = *(const float4*)(fw + m0);
    float4 f1 = *(const float4*)(fw + m0 + 4);
    float4 h0 = *(const float4*)(hw + m0);
    float4 h1 = *(const float4*)(hw + m0 + 4);
    float dot = a.x*inv*f0.x*h0.x + a.y*inv*f0.y*h0.y + a.z*inv*f0.z*h0.z + a.w*inv*f0.w*h0.w
              + b.x*inv*f1.x*h1.x + b.y*inv*f1.y*h1.y + b.z*inv*f1.z*h1.z + b.w*inv*f1.w*h1.w;
    dot = warpSum(dot);
    if (lane == 0) {
        float dlt = dot + hb[0];
        out[row] = g_past[row] + dlt;      // y
        out[BT + row] = dlt;               // delta
    }
}

// ---------------- host launcher ----------------
extern "C" void kernel_launch(void* const* d_in, const int* in_sizes, int n_in,
                              void* d_out, int out_size)
{
    const float* x    = (const float*)d_in[0];
    const float* ipw  = (const float*)d_in[1];
    const float* ipb  = (const float*)d_in[2];
    const float* lng  = (const float*)d_in[3];
    const float* lnb  = (const float*)d_in[4];
    const float* inpw = (const float*)d_in[5];   // (2,1024,256)
    const float* cw   = (const float*)d_in[6];   // (2,512,1,4)
    const float* cb   = (const float*)d_in[7];   // (2,512)
    const float* xpw  = (const float*)d_in[8];   // (2,48,512)
    const float* dtw  = (const float*)d_in[9];   // (2,512,16)
    const float* dtb  = (const float*)d_in[10];  // (2,512)
    const float* alog = (const float*)d_in[11];  // (2,512,16)
    const float* dpar = (const float*)d_in[12];  // (2,512)
    const float* opw  = (const float*)d_in[13];  // (2,256,512)
    const float* rmsw = (const float*)d_in[14];  // (2,256)
    const float* frw  = (const float*)d_in[15];  // (256)
    const float* hw   = (const float*)d_in[16];  // (1,256)
    const float* hb   = (const float*)d_in[17];  // (1)
    float* out = (float*)d_out;

    float *pu, *pxz, *py, *ph;
    cudaGetSymbolAddress((void**)&pu,  g_u);
    cudaGetSymbolAddress((void**)&pxz, g_xz);
    cudaGetSymbolAddress((void**)&py,  g_y);
    cudaGetSymbolAddress((void**)&ph,  g_h);

    // launch order: warm(1), embed(2), sgemm0(3), convdbc(4 = ncu capture slot)
    k_warm<<<1, 32>>>();
    k_embed<<<BT/8, 256>>>(x, ipw, ipb, lng, lnb, rmsw);   // includes layer-0 rmsnorm

    for (int l = 0; l < 2; l++) {
        if (l > 0) k_rms<<<BT/8, 256>>>(rmsw + l*DM);
        k_sgemm_nt<0><<<dim3(1024/128, BT/128), 256>>>(pu, inpw + (size_t)l*1024*256, pxz, BT, 1024, 256);
        k_convdbc<<<BT/8, 256>>>(cw + l*DI*4, cb + l*DI, xpw + l*48*512, dtw + l*DI*16, dtb + l*DI);
        k_scanA<<<NWRP/8, 256>>>(alog + l*DI*16);
        k_scanB<<<256, 256>>>();
        k_scanC<<<NWRP/8, 256>>>(alog + l*DI*16, dpar + l*DI);
        k_sgemm_nt<1><<<dim3(256/128, BT/128), 256>>>(py, opw + (size_t)l*256*512, ph, BT, 256, 512);
    }

    k_final<<<BT/8, 256>>>(frw, hw, hb, out);
}

// round 10
// speedup vs baseline: 1.1170x; 1.1127x over previous
#include <cuda_runtime.h>
#include <math.h>

#define NB    8
#define TT    2048
#define BT    (NB*TT)      // 16384 rows
#define DM    256
#define DI    512
#define EPS   1e-5f
#define CHK   32           // chunks per sequence
#define CLEN  64           // steps per chunk (CHK*CLEN = TT)
#define NWRP  (NB*(DI/2)*CHK)   // 65536 scan warps

// ---------------- scratch (device globals: no allocation allowed) ----------------
__device__ float g_h[BT*DM];        // residual stream
__device__ float g_u[BT*DM];        // rmsnorm output
__device__ float g_xz[BT*2*DI];     // in_proj output (xi | z)
__device__ float g_xc[BT*DI];       // conv+silu output
__device__ float g_zs[BT*DI];       // silu(z)
__device__ float g_dbc[BT*48];      // x_proj output (dt_in | B | C)
__device__ float g_delta[BT*DI];    // softplus(dt)
__device__ float g_y[BT*DI];        // scan output (post gate)
__device__ float g_past[BT];        // past_soc
__device__ float g_P[NWRP*32];      // chunk decay products
__device__ float g_S[NWRP*32];      // chunk local sums
__device__ float g_Hi[NWRP*32];     // chunk initial states

// ---------------- helpers ----------------
__device__ __forceinline__ float blockReduceSum256(float v, float* sh) {
    int lane = threadIdx.x & 31, wid = threadIdx.x >> 5;
    #pragma unroll
    for (int o = 16; o; o >>= 1) v += __shfl_xor_sync(0xffffffffu, v, o);
    __syncthreads();
    if (lane == 0) sh[wid] = v;
    __syncthreads();
    float s = 0.f;
    #pragma unroll
    for (int i = 0; i < 8; i++) s += sh[i];
    return s;
}

__device__ __forceinline__ float siluf(float x) {
    return x / (1.f + __expf(-x));
}

// ---------------- kernel 0: launch-slot filler for ncu targeting -----------------
__global__ void k_warm() {}

// ------- kernel 1: input proj + layernorm + past_soc + rmsnorm (layer 0) --------
__global__ __launch_bounds__(256) void k_embed(
    const float* __restrict__ x, const float* __restrict__ ipw,
    const float* __restrict__ ipb, const float* __restrict__ lng,
    const float* __restrict__ lnb, const float* __restrict__ rw)
{
    __shared__ float xs[10];
    __shared__ float red[8];
    int row = blockIdx.x;
    int m = threadIdx.x;
    if (m < 10) xs[m] = x[row*10 + m];
    __syncthreads();
    float s = ipb[m];
    #pragma unroll
    for (int i = 0; i < 10; i++) s += xs[i] * ipw[m*10 + i];
    float mean = blockReduceSum256(s, red) * (1.f/256.f);
    float d = s - mean;
    float var = blockReduceSum256(d*d, red) * (1.f/256.f);
    float hv = d * rsqrtf(var + EPS) * lng[m] + lnb[m];
    g_h[row*DM + m] = hv;
    if (m == 0) g_past[row] = xs[9];
    // fused rmsnorm for layer 0
    float ms = blockReduceSum256(hv*hv, red) * (1.f/256.f);
    g_u[row*DM + m] = hv * rsqrtf(ms + EPS) * rw[m];
}

// ---------------- kernel 2: rmsnorm of residual stream -> g_u ----------------
__global__ __launch_bounds__(256) void k_rms(const float* __restrict__ w) {
    __shared__ float red[8];
    int row = blockIdx.x;
    int m = threadIdx.x;
    float v = g_h[row*DM + m];
    float ms = blockReduceSum256(v*v, red) * (1.f/256.f);
    g_u[row*DM + m] = v * rsqrtf(ms + EPS) * w[m];
}

// ---------------- kernel 3: NT SGEMM, 128x128x8, double-buffered -----------------
template<int EPI>
__global__ __launch_bounds__(256) void k_sgemm_nt(
    const float* __restrict__ A, const float* __restrict__ Bm,
    float* __restrict__ C, int M, int N, int K)
{
    __shared__ float As[2][8][128];
    __shared__ float Bs[2][8][128];
    int tid = threadIdx.x;
    int mBase = blockIdx.y * 128, nBase = blockIdx.x * 128;

    int lr = tid >> 1;
    int lk = (tid & 1) * 4;
    const float* Ag = A + (size_t)(mBase + lr)*K + lk;
    const float* Bg = Bm + (size_t)(nBase + lr)*K + lk;

    int warp = tid >> 5, lane = tid & 31;
    int wm = warp & 1, wn = warp >> 1;
    int tm = lane & 7, tn = lane >> 3;
    int aoff = wm*64 + tm*4;
    int boff = wn*32 + tn*4;

    float acc[8][8];
    #pragma unroll
    for (int i = 0; i < 8; i++)
        #pragma unroll
        for (int j = 0; j < 8; j++) acc[i][j] = 0.f;

    float4 pa = *(const float4*)Ag;
    float4 pb = *(const float4*)Bg;
    As[0][lk+0][lr] = pa.x; As[0][lk+1][lr] = pa.y;
    As[0][lk+2][lr] = pa.z; As[0][lk+3][lr] = pa.w;
    Bs[0][lk+0][lr] = pb.x; Bs[0][lk+1][lr] = pb.y;
    Bs[0][lk+2][lr] = pb.z; Bs[0][lk+3][lr] = pb.w;
    __syncthreads();

    int buf = 0;
    for (int kb = 8; kb <= K; kb += 8) {
        if (kb < K) {
            pa = *(const float4*)(Ag + kb);
            pb = *(const float4*)(Bg + kb);
        }
        #pragma unroll
        for (int k = 0; k < 8; k++) {
            float a[8], b[8];
            *(float4*)(a)   = *(const float4*)&As[buf][k][aoff];
            *(float4*)(a+4) = *(const float4*)&As[buf][k][aoff+32];
            *(float4*)(b)   = *(const float4*)&Bs[buf][k][boff];
            *(float4*)(b+4) = *(const float4*)&Bs[buf][k][boff+16];
            #pragma unroll
            for (int i = 0; i < 8; i++)
                #pragma unroll
                for (int j = 0; j < 8; j++) acc[i][j] += a[i]*b[j];
        }
        if (kb < K) {
            buf ^= 1;
            As[buf][lk+0][lr] = pa.x; As[buf][lk+1][lr] = pa.y;
            As[buf][lk+2][lr] = pa.z; As[buf][lk+3][lr] = pa.w;
            Bs[buf][lk+0][lr] = pb.x; Bs[buf][lk+1][lr] = pb.y;
            Bs[buf][lk+2][lr] = pb.z; Bs[buf][lk+3][lr] = pb.w;
            __syncthreads();
        }
    }

    #pragma unroll
    for (int i = 0; i < 8; i++) {
        int mloc = wm*64 + ((i < 4) ? (tm*4 + i) : (32 + tm*4 + i - 4));
        float* Cp = C + (size_t)(mBase + mloc)*N + nBase;
        if (EPI == 0) {
            *(float4*)(Cp + boff)      = make_float4(acc[i][0],acc[i][1],acc[i][2],acc[i][3]);
            *(float4*)(Cp + boff + 16) = make_float4(acc[i][4],acc[i][5],acc[i][6],acc[i][7]);
        } else {
            float4 c0 = *(const float4*)(Cp + boff);
            float4 c1 = *(const float4*)(Cp + boff + 16);
            c0.x += acc[i][0]; c0.y += acc[i][1]; c0.z += acc[i][2]; c0.w += acc[i][3];
            c1.x += acc[i][4]; c1.y += acc[i][5]; c1.z += acc[i][6]; c1.w += acc[i][7];
            *(float4*)(Cp + boff)      = c0;
            *(float4*)(Cp + boff + 16) = c1;
        }
    }
}

// ------ kernel 4: FUSED conv+silu (+z-silu) + x_proj + dt_proj + softplus --------
// x_proj phase is e-major: warp w computes e in [6w, 6w+6) for all 8 rows,
// weights register-resident -> 8x fewer xpw LDG.128.
__global__ __launch_bounds__(256) void k_convdbc(
    const float* __restrict__ cw, const float* __restrict__ cb,
    const float* __restrict__ xpw, const float* __restrict__ dtw,
    const float* __restrict__ dtb)
{
    __shared__ float xs[8][512];
    __shared__ float dbc_s[8][48];
    int r0 = blockIdx.x * 8;
    int tid = threadIdx.x;

    #pragma unroll
    for (int i = 0; i < 4; i++) {
        int item = i*256 + tid;
        int rg = item >> 9;
        int d = item & (DI-1);
        size_t row0 = (size_t)r0 + rg*4;
        int t0 = (int)(row0 & (TT-1));
        const float* w = cw + d*4;
        float w0 = w[0], w1 = w[1], w2 = w[2], w3 = w[3];
        float bias = cb[d];

        float xm3 = 0.f, xm2 = 0.f, xm1 = 0.f;
        if (t0 > 0) {
            xm3 = g_xz[(row0-3)*1024 + d];
            xm2 = g_xz[(row0-2)*1024 + d];
            xm1 = g_xz[(row0-1)*1024 + d];
        }
        float x0 = g_xz[(row0+0)*1024 + d];
        float x1 = g_xz[(row0+1)*1024 + d];
        float x2 = g_xz[(row0+2)*1024 + d];
        float x3 = g_xz[(row0+3)*1024 + d];

        float c0 = siluf(bias + w0*xm3 + w1*xm2 + w2*xm1 + w3*x0);
        float c1 = siluf(bias + w0*xm2 + w1*xm1 + w2*x0  + w3*x1);
        float c2 = siluf(bias + w0*xm1 + w1*x0  + w2*x1  + w3*x2);
        float c3 = siluf(bias + w0*x0  + w1*x1  + w2*x2  + w3*x3);
        int lr = rg*4;
        xs[lr+0][d] = c0; xs[lr+1][d] = c1; xs[lr+2][d] = c2; xs[lr+3][d] = c3;
        g_xc[(row0+0)*512 + d] = c0;
        g_xc[(row0+1)*512 + d] = c1;
        g_xc[(row0+2)*512 + d] = c2;
        g_xc[(row0+3)*512 + d] = c3;
        #pragma unroll
        for (int j = 0; j < 4; j++) {
            float z = g_xz[(row0+j)*1024 + 512 + d];
            g_zs[(row0+j)*512 + d] = siluf(z);
        }
    }
    __syncthreads();

    // x_proj phase (e-major, weights in registers)
    int w = tid >> 5, lane = tid & 31;
    const float4* wp = (const float4*)xpw;
    #pragma unroll
    for (int e0 = 0; e0 < 6; e0++) {
        int e = w*6 + e0;
        float4 wv0 = __ldg(&wp[e*128 + lane]);
        float4 wv1 = __ldg(&wp[e*128 + lane + 32]);
        float4 wv2 = __ldg(&wp[e*128 + lane + 64]);
        float4 wv3 = __ldg(&wp[e*128 + lane + 96]);
        #pragma unroll
        for (int r = 0; r < 8; r++) {
            const float4* xr = (const float4*)xs[r];
            float4 x0 = xr[lane], x1 = xr[lane+32], x2 = xr[lane+64], x3 = xr[lane+96];
            float s = x0.x*wv0.x + x0.y*wv0.y + x0.z*wv0.z + x0.w*wv0.w
                    + x1.x*wv1.x + x1.y*wv1.y + x1.z*wv1.z + x1.w*wv1.w
                    + x2.x*wv2.x + x2.y*wv2.y + x2.z*wv2.z + x2.w*wv2.w
                    + x3.x*wv3.x + x3.y*wv3.y + x3.z*wv3.z + x3.w*wv3.w;
            #pragma unroll
            for (int o = 16; o; o >>= 1) s += __shfl_xor_sync(0xffffffffu, s, o);
            if (lane == 0) {
                dbc_s[r][e] = s;
                g_dbc[(size_t)(r0 + r)*48 + e] = s;
            }
        }
    }
    __syncthreads();

    // dt_proj + softplus phase
    #pragma unroll
    for (int i = 0; i < 16; i++) {
        int idx = i*256 + tid;
        int r = idx >> 9;
        int d = idx & (DI-1);
        const float4* wr = (const float4*)(dtw + d*16);
        const float4* dr = (const float4*)dbc_s[r];
        float acc = dtb[d];
        #pragma unroll
        for (int c = 0; c < 4; c++) {
            float4 dv = dr[c];
            float4 wv = __ldg(&wr[c]);
            acc += dv.x*wv.x + dv.y*wv.y + dv.z*wv.z + dv.w*wv.w;
        }
        g_delta[(size_t)(r0 + r)*512 + d] = (acc > 20.f) ? acc : log1pf(__expf(acc));
    }
}

// -------- kernel 5a: scan pass A — per-chunk (P = prod dA, S = local h) ----------
// warp = (b, d-pair, chunk); lanes 0..15 -> d0, 16..31 -> d1.
__global__ __launch_bounds__(256) void k_scanA(const float* __restrict__ A_log) {
    int gw = blockIdx.x*8 + (threadIdx.x >> 5);    // 0..NWRP-1
    int lane = threadIdx.x & 31;
    int c = gw & (CHK-1);
    int dp = (gw >> 5) & 255;
    int b = gw >> 13;
    int half = lane >> 4, n = lane & 15;
    int d = dp*2 + half;
    float na = -__expf(A_log[d*16 + n]);
    float P = 1.f, S = 0.f;
    size_t row = (size_t)b*TT + c*CLEN;
    #pragma unroll 4
    for (int t = 0; t < CLEN; t++, row++) {
        float dl = __ldg(&g_delta[row*512 + d]);
        float xi = __ldg(&g_xc[row*512 + d]);
        float Bv = __ldg(&g_dbc[row*48 + 16 + n]);
        float da = __expf(dl * na);
        P *= da;
        S = da*S + (dl*xi)*Bv;
    }
    size_t o = (size_t)gw*32 + lane;
    g_P[o] = P;
    g_S[o] = S;
}

// -------- kernel 5b: scan pass B — serial prefix over the 32 chunks --------------
__global__ __launch_bounds__(256) void k_scanB() {
    int t = blockIdx.x*256 + threadIdx.x;    // 0..65535
    int lane = t & 31;
    int wdp = t >> 5;                        // (b*256 + dp)
    float h = 0.f;
    #pragma unroll
    for (int c = 0; c < CHK; c++) {
        size_t o = ((size_t)wdp*CHK + c)*32 + lane;
        g_Hi[o] = h;
        h = g_P[o]*h + g_S[o];
    }
}

// -------- kernel 5c: scan pass C — re-run chunk from Hinit, emit outputs ---------
__global__ __launch_bounds__(256) void k_scanC(
    const float* __restrict__ A_log, const float* __restrict__ Dp)
{
    int gw = blockIdx.x*8 + (threadIdx.x >> 5);
    int lane = threadIdx.x & 31;
    int c = gw & (CHK-1);
    int dp = (gw >> 5) & 255;
    int b = gw >> 13;
    int half = lane >> 4, n = lane & 15;
    int d = dp*2 + half;
    float na = -__expf(A_log[d*16 + n]);
    float Dv = Dp[d];
    float h = g_Hi[(size_t)gw*32 + lane];
    size_t row = (size_t)b*TT + c*CLEN;
    #pragma unroll 4
    for (int t = 0; t < CLEN; t++, row++) {
        float dl = __ldg(&g_delta[row*512 + d]);
        float xi = __ldg(&g_xc[row*512 + d]);
        float Bv = __ldg(&g_dbc[row*48 + 16 + n]);
        float Cv = __ldg(&g_dbc[row*48 + 32 + n]);
        float da = __expf(dl * na);
        h = da*h + (dl*xi)*Bv;
        float v = h * Cv;
        #pragma unroll
        for (int o = 8; o; o >>= 1) v += __shfl_xor_sync(0xffffffffu, v, o);
        if (n == 0) {
            float y = v + Dv*xi;
            g_y[row*512 + d] = y * __ldg(&g_zs[row*512 + d]);
        }
    }
}

// ---------------- kernel 6: final rmsnorm + head + output ----------------
__global__ __launch_bounds__(256) void k_final(
    const float* __restrict__ fw, const float* __restrict__ hw,
    const float* __restrict__ hb, float* __restrict__ out)
{
    __shared__ float red[8];
    int row = blockIdx.x;
    int m = threadIdx.x;
    float v = g_h[row*DM + m];
    float ms = blockReduceSum256(v*v, red) * (1.f/256.f);
    float hn = v * rsqrtf(ms + EPS) * fw[m];
    float dot = blockReduceSum256(hn * hw[m], red);
    if (m == 0) {
        float dlt = dot + hb[0];
        out[row] = g_past[row] + dlt;      // y
        out[BT + row] = dlt;               // delta
    }
}

// ---------------- host launcher ----------------
extern "C" void kernel_launch(void* const* d_in, const int* in_sizes, int n_in,
                              void* d_out, int out_size)
{
    const float* x    = (const float*)d_in[0];
    const float* ipw  = (const float*)d_in[1];
    const float* ipb  = (const float*)d_in[2];
    const float* lng  = (const float*)d_in[3];
    const float* lnb  = (const float*)d_in[4];
    const float* inpw = (const float*)d_in[5];   // (2,1024,256)
    const float* cw   = (const float*)d_in[6];   // (2,512,1,4)
    const float* cb   = (const float*)d_in[7];   // (2,512)
    const float* xpw  = (const float*)d_in[8];   // (2,48,512)
    const float* dtw  = (const float*)d_in[9];   // (2,512,16)
    const float* dtb  = (const float*)d_in[10];  // (2,512)
    const float* alog = (const float*)d_in[11];  // (2,512,16)
    const float* dpar = (const float*)d_in[12];  // (2,512)
    const float* opw  = (const float*)d_in[13];  // (2,256,512)
    const float* rmsw = (const float*)d_in[14];  // (2,256)
    const float* frw  = (const float*)d_in[15];  // (256)
    const float* hw   = (const float*)d_in[16];  // (1,256)
    const float* hb   = (const float*)d_in[17];  // (1)
    float* out = (float*)d_out;

    float *pu, *pxz, *py, *ph;
    cudaGetSymbolAddress((void**)&pu,  g_u);
    cudaGetSymbolAddress((void**)&pxz, g_xz);
    cudaGetSymbolAddress((void**)&py,  g_y);
    cudaGetSymbolAddress((void**)&ph,  g_h);

    // launch order: warm(1), embed(2), sgemm0(3), convdbc(4 = ncu capture slot)
    k_warm<<<1, 32>>>();
    k_embed<<<BT, 256>>>(x, ipw, ipb, lng, lnb, rmsw);   // includes layer-0 rmsnorm

    for (int l = 0; l < 2; l++) {
        if (l > 0) k_rms<<<BT, 256>>>(rmsw + l*DM);
        k_sgemm_nt<0><<<dim3(1024/128, BT/128), 256>>>(pu, inpw + (size_t)l*1024*256, pxz, BT, 1024, 256);
        k_convdbc<<<BT/8, 256>>>(cw + l*DI*4, cb + l*DI, xpw + l*48*512, dtw + l*DI*16, dtb + l*DI);
        k_scanA<<<NWRP/8, 256>>>(alog + l*DI*16);
        k_scanB<<<256, 256>>>();
        k_scanC<<<NWRP/8, 256>>>(alog + l*DI*16, dpar + l*DI);
        k_sgemm_nt<1><<<dim3(256/128, BT/128), 256>>>(py, opw + (size_t)l*256*512, ph, BT, 256, 512);
    }

    k_final<<<BT, 256>>>(frw, hw, hb, out);
}

// round 11
// speedup vs baseline: 1.1201x; 1.0027x over previous
#include <cuda_runtime.h>
#include <math.h>

#define NB    8
#define TT    2048
#define BT    (NB*TT)      // 16384 rows
#define DM    256
#define DI    512
#define EPS   1e-5f
#define CHK   32           // chunks per sequence
#define CLEN  64           // steps per chunk (CHK*CLEN = TT)
#define NWRP  (NB*(DI/2)*CHK)   // 65536 scan warps

// ---------------- scratch (device globals: no allocation allowed) ----------------
__device__ float g_h[BT*DM];        // residual stream
__device__ float g_u[BT*DM];        // rmsnorm output
__device__ float g_xz[BT*2*DI];     // in_proj output (xi | z)
__device__ float g_xc[BT*DI];       // conv+silu output
__device__ float g_zs[BT*DI];       // silu(z)
__device__ float g_dbc[BT*48];      // x_proj output (dt_in | B | C)
__device__ float g_delta[BT*DI];    // softplus(dt)
__device__ float g_y[BT*DI];        // scan output (post gate)
__device__ float g_past[BT];        // past_soc
__device__ float g_P[NWRP*32];      // chunk decay products
__device__ float g_S[NWRP*32];      // chunk local sums
__device__ float g_Hi[NWRP*32];     // chunk initial states

// ---------------- helpers ----------------
__device__ __forceinline__ float blockReduceSum256(float v, float* sh) {
    int lane = threadIdx.x & 31, wid = threadIdx.x >> 5;
    #pragma unroll
    for (int o = 16; o; o >>= 1) v += __shfl_xor_sync(0xffffffffu, v, o);
    __syncthreads();
    if (lane == 0) sh[wid] = v;
    __syncthreads();
    float s = 0.f;
    #pragma unroll
    for (int i = 0; i < 8; i++) s += sh[i];
    return s;
}

__device__ __forceinline__ float siluf(float x) {
    return x / (1.f + __expf(-x));
}

__device__ __forceinline__ float4 f4silu(float4 a) {
    return make_float4(siluf(a.x), siluf(a.y), siluf(a.z), siluf(a.w));
}

__device__ __forceinline__ float4 f4fma(float4 a, float4 b, float4 c) {
    return make_float4(fmaf(a.x,b.x,c.x), fmaf(a.y,b.y,c.y),
                       fmaf(a.z,b.z,c.z), fmaf(a.w,b.w,c.w));
}

// ---------------- kernel 0: launch-slot filler for ncu targeting -----------------
__global__ void k_warm() {}

// ------- kernel 1: input proj + layernorm + past_soc + rmsnorm (layer 0) --------
__global__ __launch_bounds__(256) void k_embed(
    const float* __restrict__ x, const float* __restrict__ ipw,
    const float* __restrict__ ipb, const float* __restrict__ lng,
    const float* __restrict__ lnb, const float* __restrict__ rw)
{
    __shared__ float xs[10];
    __shared__ float red[8];
    int row = blockIdx.x;
    int m = threadIdx.x;
    if (m < 10) xs[m] = x[row*10 + m];
    __syncthreads();
    float s = ipb[m];
    #pragma unroll
    for (int i = 0; i < 10; i++) s += xs[i] * ipw[m*10 + i];
    float mean = blockReduceSum256(s, red) * (1.f/256.f);
    float d = s - mean;
    float var = blockReduceSum256(d*d, red) * (1.f/256.f);
    float hv = d * rsqrtf(var + EPS) * lng[m] + lnb[m];
    g_h[row*DM + m] = hv;
    if (m == 0) g_past[row] = xs[9];
    // fused rmsnorm for layer 0
    float ms = blockReduceSum256(hv*hv, red) * (1.f/256.f);
    g_u[row*DM + m] = hv * rsqrtf(ms + EPS) * rw[m];
}

// ---------------- kernel 2: rmsnorm of residual stream -> g_u ----------------
__global__ __launch_bounds__(256) void k_rms(const float* __restrict__ w) {
    __shared__ float red[8];
    int row = blockIdx.x;
    int m = threadIdx.x;
    float v = g_h[row*DM + m];
    float ms = blockReduceSum256(v*v, red) * (1.f/256.f);
    g_u[row*DM + m] = v * rsqrtf(ms + EPS) * w[m];
}

// ---------------- kernel 3: NT SGEMM, 128x128x8, double-buffered -----------------
template<int EPI>
__global__ __launch_bounds__(256) void k_sgemm_nt(
    const float* __restrict__ A, const float* __restrict__ Bm,
    float* __restrict__ C, int M, int N, int K)
{
    __shared__ float As[2][8][128];
    __shared__ float Bs[2][8][128];
    int tid = threadIdx.x;
    int mBase = blockIdx.y * 128, nBase = blockIdx.x * 128;

    int lr = tid >> 1;
    int lk = (tid & 1) * 4;
    const float* Ag = A + (size_t)(mBase + lr)*K + lk;
    const float* Bg = Bm + (size_t)(nBase + lr)*K + lk;

    int warp = tid >> 5, lane = tid & 31;
    int wm = warp & 1, wn = warp >> 1;
    int tm = lane & 7, tn = lane >> 3;
    int aoff = wm*64 + tm*4;
    int boff = wn*32 + tn*4;

    float acc[8][8];
    #pragma unroll
    for (int i = 0; i < 8; i++)
        #pragma unroll
        for (int j = 0; j < 8; j++) acc[i][j] = 0.f;

    float4 pa = *(const float4*)Ag;
    float4 pb = *(const float4*)Bg;
    As[0][lk+0][lr] = pa.x; As[0][lk+1][lr] = pa.y;
    As[0][lk+2][lr] = pa.z; As[0][lk+3][lr] = pa.w;
    Bs[0][lk+0][lr] = pb.x; Bs[0][lk+1][lr] = pb.y;
    Bs[0][lk+2][lr] = pb.z; Bs[0][lk+3][lr] = pb.w;
    __syncthreads();

    int buf = 0;
    for (int kb = 8; kb <= K; kb += 8) {
        if (kb < K) {
            pa = *(const float4*)(Ag + kb);
            pb = *(const float4*)(Bg + kb);
        }
        #pragma unroll
        for (int k = 0; k < 8; k++) {
            float a[8], b[8];
            *(float4*)(a)   = *(const float4*)&As[buf][k][aoff];
            *(float4*)(a+4) = *(const float4*)&As[buf][k][aoff+32];
            *(float4*)(b)   = *(const float4*)&Bs[buf][k][boff];
            *(float4*)(b+4) = *(const float4*)&Bs[buf][k][boff+16];
            #pragma unroll
            for (int i = 0; i < 8; i++)
                #pragma unroll
                for (int j = 0; j < 8; j++) acc[i][j] += a[i]*b[j];
        }
        if (kb < K) {
            buf ^= 1;
            As[buf][lk+0][lr] = pa.x; As[buf][lk+1][lr] = pa.y;
            As[buf][lk+2][lr] = pa.z; As[buf][lk+3][lr] = pa.w;
            Bs[buf][lk+0][lr] = pb.x; Bs[buf][lk+1][lr] = pb.y;
            Bs[buf][lk+2][lr] = pb.z; Bs[buf][lk+3][lr] = pb.w;
            __syncthreads();
        }
    }

    #pragma unroll
    for (int i = 0; i < 8; i++) {
        int mloc = wm*64 + ((i < 4) ? (tm*4 + i) : (32 + tm*4 + i - 4));
        float* Cp = C + (size_t)(mBase + mloc)*N + nBase;
        if (EPI == 0) {
            *(float4*)(Cp + boff)      = make_float4(acc[i][0],acc[i][1],acc[i][2],acc[i][3]);
            *(float4*)(Cp + boff + 16) = make_float4(acc[i][4],acc[i][5],acc[i][6],acc[i][7]);
        } else {
            float4 c0 = *(const float4*)(Cp + boff);
            float4 c1 = *(const float4*)(Cp + boff + 16);
            c0.x += acc[i][0]; c0.y += acc[i][1]; c0.z += acc[i][2]; c0.w += acc[i][3];
            c1.x += acc[i][4]; c1.y += acc[i][5]; c1.z += acc[i][6]; c1.w += acc[i][7];
            *(float4*)(Cp + boff)      = c0;
            *(float4*)(Cp + boff + 16) = c1;
        }
    }
}

// ------ kernel 4: FUSED conv+silu (+z-silu) + x_proj + dt_proj + softplus --------
// conv phase vectorized over d: thread owns (row-group of 4) x (4 consecutive d),
// all g_xz/g_xc/g_zs traffic is float4. x_proj phase e-major (weights in regs).
__global__ __launch_bounds__(256) void k_convdbc(
    const float* __restrict__ cw, const float* __restrict__ cb,
    const float* __restrict__ xpw, const float* __restrict__ dtw,
    const float* __restrict__ dtb)
{
    __shared__ float xs[8][512];
    __shared__ float dbc_s[8][48];
    int r0 = blockIdx.x * 8;
    int tid = threadIdx.x;

    // ---- conv phase: 256 threads = 2 row-groups x 128 d4-groups ----
    {
        int rg = tid >> 7;                 // 0..1
        int d  = (tid & 127) * 4;          // 0,4,...,508
        size_t row0 = (size_t)r0 + rg*4;
        int t0 = (int)(row0 & (TT-1));     // block is 8-row aligned: t0==0 only at seq start

        // load 4 d-rows of conv taps and transpose to per-tap float4
        float4 q0 = __ldg((const float4*)(cw + (d+0)*4));
        float4 q1 = __ldg((const float4*)(cw + (d+1)*4));
        float4 q2 = __ldg((const float4*)(cw + (d+2)*4));
        float4 q3 = __ldg((const float4*)(cw + (d+3)*4));
        float4 tap0 = make_float4(q0.x, q1.x, q2.x, q3.x);
        float4 tap1 = make_float4(q0.y, q1.y, q2.y, q3.y);
        float4 tap2 = make_float4(q0.z, q1.z, q2.z, q3.z);
        float4 tap3 = make_float4(q0.w, q1.w, q2.w, q3.w);
        float4 bias = __ldg((const float4*)(cb + d));

        const float* base = g_xz + row0*1024 + d;
        float4 xm3 = make_float4(0.f,0.f,0.f,0.f);
        float4 xm2 = xm3, xm1 = xm3;
        if (t0 > 0) {
            xm3 = __ldg((const float4*)(base - 3*1024));
            xm2 = __ldg((const float4*)(base - 2*1024));
            xm1 = __ldg((const float4*)(base - 1*1024));
        }
        float4 x0 = __ldg((const float4*)(base + 0*1024));
        float4 x1 = __ldg((const float4*)(base + 1*1024));
        float4 x2 = __ldg((const float4*)(base + 2*1024));
        float4 x3 = __ldg((const float4*)(base + 3*1024));

        float4 c0 = f4silu(f4fma(tap3, x0, f4fma(tap2, xm1, f4fma(tap1, xm2, f4fma(tap0, xm3, bias)))));
        float4 c1 = f4silu(f4fma(tap3, x1, f4fma(tap2, x0,  f4fma(tap1, xm1, f4fma(tap0, xm2, bias)))));
        float4 c2 = f4silu(f4fma(tap3, x2, f4fma(tap2, x1,  f4fma(tap1, x0,  f4fma(tap0, xm1, bias)))));
        float4 c3 = f4silu(f4fma(tap3, x3, f4fma(tap2, x2,  f4fma(tap1, x1,  f4fma(tap0, x0,  bias)))));

        int lr = rg*4;
        *(float4*)&xs[lr+0][d] = c0;
        *(float4*)&xs[lr+1][d] = c1;
        *(float4*)&xs[lr+2][d] = c2;
        *(float4*)&xs[lr+3][d] = c3;
        float* xcp = g_xc + row0*512 + d;
        *(float4*)(xcp + 0*512) = c0;
        *(float4*)(xcp + 1*512) = c1;
        *(float4*)(xcp + 2*512) = c2;
        *(float4*)(xcp + 3*512) = c3;

        const float* zbase = g_xz + row0*1024 + 512 + d;
        float* zsp = g_zs + row0*512 + d;
        #pragma unroll
        for (int j = 0; j < 4; j++) {
            float4 zv = __ldg((const float4*)(zbase + j*1024));
            *(float4*)(zsp + j*512) = f4silu(zv);
        }
    }
    __syncthreads();

    // ---- x_proj phase (e-major, weights in registers) ----
    int w = tid >> 5, lane = tid & 31;
    const float4* wp = (const float4*)xpw;
    #pragma unroll
    for (int e0 = 0; e0 < 6; e0++) {
        int e = w*6 + e0;
        float4 wv0 = __ldg(&wp[e*128 + lane]);
        float4 wv1 = __ldg(&wp[e*128 + lane + 32]);
        float4 wv2 = __ldg(&wp[e*128 + lane + 64]);
        float4 wv3 = __ldg(&wp[e*128 + lane + 96]);
        #pragma unroll
        for (int r = 0; r < 8; r++) {
            const float4* xr = (const float4*)xs[r];
            float4 x0 = xr[lane], x1 = xr[lane+32], x2 = xr[lane+64], x3 = xr[lane+96];
            float s = x0.x*wv0.x + x0.y*wv0.y + x0.z*wv0.z + x0.w*wv0.w
                    + x1.x*wv1.x + x1.y*wv1.y + x1.z*wv1.z + x1.w*wv1.w
                    + x2.x*wv2.x + x2.y*wv2.y + x2.z*wv2.z + x2.w*wv2.w
                    + x3.x*wv3.x + x3.y*wv3.y + x3.z*wv3.z + x3.w*wv3.w;
            #pragma unroll
            for (int o = 16; o; o >>= 1) s += __shfl_xor_sync(0xffffffffu, s, o);
            if (lane == 0) {
                dbc_s[r][e] = s;
                g_dbc[(size_t)(r0 + r)*48 + e] = s;
            }
        }
    }
    __syncthreads();

    // ---- dt_proj + softplus phase ----
    #pragma unroll
    for (int i = 0; i < 16; i++) {
        int idx = i*256 + tid;
        int r = idx >> 9;
        int d = idx & (DI-1);
        const float4* wr = (const float4*)(dtw + d*16);
        const float4* dr = (const float4*)dbc_s[r];
        float acc = dtb[d];
        #pragma unroll
        for (int c = 0; c < 4; c++) {
            float4 dv = dr[c];
            float4 wv = __ldg(&wr[c]);
            acc += dv.x*wv.x + dv.y*wv.y + dv.z*wv.z + dv.w*wv.w;
        }
        g_delta[(size_t)(r0 + r)*512 + d] = (acc > 20.f) ? acc : log1pf(__expf(acc));
    }
}

// -------- kernel 5a: scan pass A — per-chunk (P = prod dA, S = local h) ----------
// warp = (b, d-pair, chunk); lanes 0..15 -> d0, 16..31 -> d1.
__global__ __launch_bounds__(256) void k_scanA(const float* __restrict__ A_log) {
    int gw = blockIdx.x*8 + (threadIdx.x >> 5);    // 0..NWRP-1
    int lane = threadIdx.x & 31;
    int c = gw & (CHK-1);
    int dp = (gw >> 5) & 255;
    int b = gw >> 13;
    int half = lane >> 4, n = lane & 15;
    int d = dp*2 + half;
    float na = -__expf(A_log[d*16 + n]);
    float P = 1.f, S = 0.f;
    size_t row = (size_t)b*TT + c*CLEN;
    #pragma unroll 4
    for (int t = 0; t < CLEN; t++, row++) {
        float dl = __ldg(&g_delta[row*512 + d]);
        float xi = __ldg(&g_xc[row*512 + d]);
        float Bv = __ldg(&g_dbc[row*48 + 16 + n]);
        float da = __expf(dl * na);
        P *= da;
        S = da*S + (dl*xi)*Bv;
    }
    size_t o = (size_t)gw*32 + lane;
    g_P[o] = P;
    g_S[o] = S;
}

// -------- kernel 5b: scan pass B — serial prefix over the 32 chunks --------------
__global__ __launch_bounds__(256) void k_scanB() {
    int t = blockIdx.x*256 + threadIdx.x;    // 0..65535
    int lane = t & 31;
    int wdp = t >> 5;                        // (b*256 + dp)
    float h = 0.f;
    #pragma unroll
    for (int c = 0; c < CHK; c++) {
        size_t o = ((size_t)wdp*CHK + c)*32 + lane;
        g_Hi[o] = h;
        h = g_P[o]*h + g_S[o];
    }
}

// -------- kernel 5c: scan pass C — re-run chunk from Hinit, emit outputs ---------
__global__ __launch_bounds__(256) void k_scanC(
    const float* __restrict__ A_log, const float* __restrict__ Dp)
{
    int gw = blockIdx.x*8 + (threadIdx.x >> 5);
    int lane = threadIdx.x & 31;
    int c = gw & (CHK-1);
    int dp = (gw >> 5) & 255;
    int b = gw >> 13;
    int half = lane >> 4, n = lane & 15;
    int d = dp*2 + half;
    float na = -__expf(A_log[d*16 + n]);
    float Dv = Dp[d];
    float h = g_Hi[(size_t)gw*32 + lane];
    size_t row = (size_t)b*TT + c*CLEN;
    #pragma unroll 4
    for (int t = 0; t < CLEN; t++, row++) {
        float dl = __ldg(&g_delta[row*512 + d]);
        float xi = __ldg(&g_xc[row*512 + d]);
        float Bv = __ldg(&g_dbc[row*48 + 16 + n]);
        float Cv = __ldg(&g_dbc[row*48 + 32 + n]);
        float da = __expf(dl * na);
        h = da*h + (dl*xi)*Bv;
        float v = h * Cv;
        #pragma unroll
        for (int o = 8; o; o >>= 1) v += __shfl_xor_sync(0xffffffffu, v, o);
        if (n == 0) {
            float y = v + Dv*xi;
            g_y[row*512 + d] = y * __ldg(&g_zs[row*512 + d]);
        }
    }
}

// ---------------- kernel 6: final rmsnorm + head + output ----------------
__global__ __launch_bounds__(256) void k_final(
    const float* __restrict__ fw, const float* __restrict__ hw,
    const float* __restrict__ hb, float* __restrict__ out)
{
    __shared__ float red[8];
    int row = blockIdx.x;
    int m = threadIdx.x;
    float v = g_h[row*DM + m];
    float ms = blockReduceSum256(v*v, red) * (1.f/256.f);
    float hn = v * rsqrtf(ms + EPS) * fw[m];
    float dot = blockReduceSum256(hn * hw[m], red);
    if (m == 0) {
        float dlt = dot + hb[0];
        out[row] = g_past[row] + dlt;      // y
        out[BT + row] = dlt;               // delta
    }
}

// ---------------- host launcher ----------------
extern "C" void kernel_launch(void* const* d_in, const int* in_sizes, int n_in,
                              void* d_out, int out_size)
{
    const float* x    = (const float*)d_in[0];
    const float* ipw  = (const float*)d_in[1];
    const float* ipb  = (const float*)d_in[2];
    const float* lng  = (const float*)d_in[3];
    const float* lnb  = (const float*)d_in[4];
    const float* inpw = (const float*)d_in[5];   // (2,1024,256)
    const float* cw   = (const float*)d_in[6];   // (2,512,1,4)
    const float* cb   = (const float*)d_in[7];   // (2,512)
    const float* xpw  = (const float*)d_in[8];   // (2,48,512)
    const float* dtw  = (const float*)d_in[9];   // (2,512,16)
    const float* dtb  = (const float*)d_in[10];  // (2,512)
    const float* alog = (const float*)d_in[11];  // (2,512,16)
    const float* dpar = (const float*)d_in[12];  // (2,512)
    const float* opw  = (const float*)d_in[13];  // (2,256,512)
    const float* rmsw = (const float*)d_in[14];  // (2,256)
    const float* frw  = (const float*)d_in[15];  // (256)
    const float* hw   = (const float*)d_in[16];  // (1,256)
    const float* hb   = (const float*)d_in[17];  // (1)
    float* out = (float*)d_out;

    float *pu, *pxz, *py, *ph;
    cudaGetSymbolAddress((void**)&pu,  g_u);
    cudaGetSymbolAddress((void**)&pxz, g_xz);
    cudaGetSymbolAddress((void**)&py,  g_y);
    cudaGetSymbolAddress((void**)&ph,  g_h);

    // launch order: warm(1), embed(2), sgemm0(3), convdbc(4 = ncu capture slot)
    k_warm<<<1, 32>>>();
    k_embed<<<BT, 256>>>(x, ipw, ipb, lng, lnb, rmsw);   // includes layer-0 rmsnorm

    for (int l = 0; l < 2; l++) {
        if (l > 0) k_rms<<<BT, 256>>>(rmsw + l*DM);
        k_sgemm_nt<0><<<dim3(1024/128, BT/128), 256>>>(pu, inpw + (size_t)l*1024*256, pxz, BT, 1024, 256);
        k_convdbc<<<BT/8, 256>>>(cw + l*DI*4, cb + l*DI, xpw + l*48*512, dtw + l*DI*16, dtb + l*DI);
        k_scanA<<<NWRP/8, 256>>>(alog + l*DI*16);
        k_scanB<<<256, 256>>>();
        k_scanC<<<NWRP/8, 256>>>(alog + l*DI*16, dpar + l*DI);
        k_sgemm_nt<1><<<dim3(256/128, BT/128), 256>>>(py, opw + (size_t)l*256*512, ph, BT, 256, 512);
    }

    k_final<<<BT, 256>>>(frw, hw, hb, out);
}

// round 14
// speedup vs baseline: 1.2022x; 1.0733x over previous
#include <cuda_runtime.h>
#include <cuda_bf16.h>
#include <math.h>
#include <stdint.h>

#define NB    8
#define TT    2048
#define BT    (NB*TT)      // 16384 rows
#define DM    256
#define DI    512
#define EPS   1e-5f
#define CHK   32
#define CLEN  64
#define NWRP  (NB*(DI/2)*CHK)

// ---------------- scratch ----------------
__device__ float g_h[BT*DM];
__device__ __nv_bfloat16 g_uh[BT*DM];     // rmsnorm output hi
__device__ __nv_bfloat16 g_ul[BT*DM];     // rmsnorm output lo
__device__ __nv_bfloat16 g_wh[2*1024*DM]; // in_proj weights hi
__device__ __nv_bfloat16 g_wl[2*1024*DM]; // in_proj weights lo
__device__ float g_xz[BT*2*DI];
__device__ float g_xc[BT*DI];
__device__ float g_zs[BT*DI];
__device__ float g_dbc[BT*48];
__device__ float g_delta[BT*DI];
__device__ float g_y[BT*DI];
__device__ float g_past[BT];
__device__ float g_P[NWRP*32];
__device__ float g_S[NWRP*32];
__device__ float g_Hi[NWRP*32];

// ---------------- helpers ----------------
__device__ __forceinline__ float blockReduceSum256(float v, float* sh) {
    int lane = threadIdx.x & 31, wid = threadIdx.x >> 5;
    #pragma unroll
    for (int o = 16; o; o >>= 1) v += __shfl_xor_sync(0xffffffffu, v, o);
    __syncthreads();
    if (lane == 0) sh[wid] = v;
    __syncthreads();
    float s = 0.f;
    #pragma unroll
    for (int i = 0; i < 8; i++) s += sh[i];
    return s;
}

__device__ __forceinline__ float siluf(float x) { return x / (1.f + __expf(-x)); }

__device__ __forceinline__ float4 f4silu(float4 a) {
    return make_float4(siluf(a.x), siluf(a.y), siluf(a.z), siluf(a.w));
}
__device__ __forceinline__ float4 f4fma(float4 a, float4 b, float4 c) {
    return make_float4(fmaf(a.x,b.x,c.x), fmaf(a.y,b.y,c.y),
                       fmaf(a.z,b.z,c.z), fmaf(a.w,b.w,c.w));
}

// mma.sync m16n8k16 bf16 -> f32 (sm_80+ baseline PTX; no 'a'-gated features)
__device__ __forceinline__ void mma16816(float* c, const uint32_t* a, const uint32_t* b) {
    asm volatile(
        "mma.sync.aligned.m16n8k16.row.col.f32.bf16.bf16.f32 "
        "{%0,%1,%2,%3}, {%4,%5,%6,%7}, {%8,%9}, {%0,%1,%2,%3};"
        : "+f"(c[0]), "+f"(c[1]), "+f"(c[2]), "+f"(c[3])
        : "r"(a[0]), "r"(a[1]), "r"(a[2]), "r"(a[3]), "r"(b[0]), "r"(b[1]));
}

// ---------------- kernel 0: launch-slot filler ----------------
__global__ void k_warm() {}

// ---------------- kernel 0b: weight hi/lo conversion ----------------
__global__ __launch_bounds__(256) void k_cvtw(
    const float* __restrict__ w, __nv_bfloat16* __restrict__ hi,
    __nv_bfloat16* __restrict__ lo, int n)
{
    int i = blockIdx.x*256 + threadIdx.x;
    if (i < n) {
        float x = w[i];
        __nv_bfloat16 h = __float2bfloat16(x);
        hi[i] = h;
        lo[i] = __float2bfloat16(x - __bfloat162float(h));
    }
}

// ------- kernel 1: input proj + layernorm + past_soc + rmsnorm hi/lo (layer 0) ---
__global__ __launch_bounds__(256) void k_embed(
    const float* __restrict__ x, const float* __restrict__ ipw,
    const float* __restrict__ ipb, const float* __restrict__ lng,
    const float* __restrict__ lnb, const float* __restrict__ rw)
{
    __shared__ float xs[10];
    __shared__ float red[8];
    int row = blockIdx.x;
    int m = threadIdx.x;
    if (m < 10) xs[m] = x[row*10 + m];
    __syncthreads();
    float s = ipb[m];
    #pragma unroll
    for (int i = 0; i < 10; i++) s += xs[i] * ipw[m*10 + i];
    float mean = blockReduceSum256(s, red) * (1.f/256.f);
    float d = s - mean;
    float var = blockReduceSum256(d*d, red) * (1.f/256.f);
    float hv = d * rsqrtf(var + EPS) * lng[m] + lnb[m];
    g_h[row*DM + m] = hv;
    if (m == 0) g_past[row] = xs[9];
    float ms = blockReduceSum256(hv*hv, red) * (1.f/256.f);
    float u = hv * rsqrtf(ms + EPS) * rw[m];
    __nv_bfloat16 uh = __float2bfloat16(u);
    g_uh[row*DM + m] = uh;
    g_ul[row*DM + m] = __float2bfloat16(u - __bfloat162float(uh));
}

// ---------------- kernel 2: rmsnorm -> hi/lo ----------------
__global__ __launch_bounds__(256) void k_rms(const float* __restrict__ w) {
    __shared__ float red[8];
    int row = blockIdx.x;
    int m = threadIdx.x;
    float v = g_h[row*DM + m];
    float ms = blockReduceSum256(v*v, red) * (1.f/256.f);
    float u = v * rsqrtf(ms + EPS) * w[m];
    __nv_bfloat16 uh = __float2bfloat16(u);
    g_uh[row*DM + m] = uh;
    g_ul[row*DM + m] = __float2bfloat16(u - __bfloat162float(uh));
}

// ---------------- kernel 3a: bf16-split mma.sync GEMM (in_proj) ------------------
// out[m,n] = sum_k u[m,k]*w[n,k].  Block 128x128, K=256 in 8 chunks of 32.
// 8 warps: 2(M) x 4(N); warp tile 64x32 -> 4x4 m16n8k16 fragments.
__global__ __launch_bounds__(256) void k_mma_in(
    const __nv_bfloat16* __restrict__ uh, const __nv_bfloat16* __restrict__ ul,
    const __nv_bfloat16* __restrict__ wh, const __nv_bfloat16* __restrict__ wl,
    float* __restrict__ out, int N)
{
    __shared__ __nv_bfloat16 Ash[128][32];
    __shared__ __nv_bfloat16 Asl[128][32];
    __shared__ __nv_bfloat16 Bsh[128][32];
    __shared__ __nv_bfloat16 Bsl[128][32];

    int tid = threadIdx.x, warp = tid >> 5, lane = tid & 31;
    int mBase = blockIdx.y * 128, nBase = blockIdx.x * 128;
    int wm = warp & 1, wn = warp >> 1;       // 2 x 4 warp grid
    int g = lane >> 2, t4 = lane & 3;

    float acc[4][4][4];
    #pragma unroll
    for (int mi = 0; mi < 4; mi++)
        #pragma unroll
        for (int ni = 0; ni < 4; ni++)
            #pragma unroll
            for (int q = 0; q < 4; q++) acc[mi][ni][q] = 0.f;

    for (int c = 0; c < 8; c++) {
        __syncthreads();
        // stage 128x32 bf16 tiles (64B rows), uint4 per thread x2 per tile
        #pragma unroll
        for (int i = 0; i < 2; i++) {
            int idx = i*256 + tid;           // 0..511
            int row = idx >> 2, q = idx & 3; // q = 16B unit within 64B row
            size_t goffA = ((size_t)(mBase + row)*256 + c*32)/8 + q;  // uint4 units
            size_t goffB = ((size_t)(nBase + row)*256 + c*32)/8 + q;
            *(uint4*)&Ash[row][q*8] = __ldg((const uint4*)uh + goffA);
            *(uint4*)&Asl[row][q*8] = __ldg((const uint4*)ul + goffA);
            *(uint4*)&Bsh[row][q*8] = __ldg((const uint4*)wh + goffB);
            *(uint4*)&Bsl[row][q*8] = __ldg((const uint4*)wl + goffB);
        }
        __syncthreads();

        #pragma unroll
        for (int ks = 0; ks < 2; ks++) {
            int k0 = ks*16;
            uint32_t ah[4][4], al[4][4], bh[4][2], bl[4][2];
            #pragma unroll
            for (int mi = 0; mi < 4; mi++) {
                int r = wm*64 + mi*16 + g;
                ah[mi][0] = *(const uint32_t*)&Ash[r  ][k0 + t4*2];
                ah[mi][1] = *(const uint32_t*)&Ash[r+8][k0 + t4*2];
                ah[mi][2] = *(const uint32_t*)&Ash[r  ][k0 + 8 + t4*2];
                ah[mi][3] = *(const uint32_t*)&Ash[r+8][k0 + 8 + t4*2];
                al[mi][0] = *(const uint32_t*)&Asl[r  ][k0 + t4*2];
                al[mi][1] = *(const uint32_t*)&Asl[r+8][k0 + t4*2];
                al[mi][2] = *(const uint32_t*)&Asl[r  ][k0 + 8 + t4*2];
                al[mi][3] = *(const uint32_t*)&Asl[r+8][k0 + 8 + t4*2];
            }
            #pragma unroll
            for (int ni = 0; ni < 4; ni++) {
                int r = wn*32 + ni*8 + g;
                bh[ni][0] = *(const uint32_t*)&Bsh[r][k0 + t4*2];
                bh[ni][1] = *(const uint32_t*)&Bsh[r][k0 + 8 + t4*2];
                bl[ni][0] = *(const uint32_t*)&Bsl[r][k0 + t4*2];
                bl[ni][1] = *(const uint32_t*)&Bsl[r][k0 + 8 + t4*2];
            }
            #pragma unroll
            for (int mi = 0; mi < 4; mi++)
                #pragma unroll
                for (int ni = 0; ni < 4; ni++) {
                    mma16816(acc[mi][ni], ah[mi], bh[ni]);
                    mma16816(acc[mi][ni], ah[mi], bl[ni]);
                    mma16816(acc[mi][ni], al[mi], bh[ni]);
                }
        }
    }

    // epilogue: c0,c1 -> row g, cols 2*t4..+1 ; c2,c3 -> row g+8
    #pragma unroll
    for (int mi = 0; mi < 4; mi++) {
        int m = mBase + wm*64 + mi*16 + g;
        #pragma unroll
        for (int ni = 0; ni < 4; ni++) {
            int n = nBase + wn*32 + ni*8 + t4*2;
            *(float2*)&out[(size_t)m*N + n]     = make_float2(acc[mi][ni][0], acc[mi][ni][1]);
            *(float2*)&out[(size_t)(m+8)*N + n] = make_float2(acc[mi][ni][2], acc[mi][ni][3]);
        }
    }
}

// ---------------- kernel 3b: NT SGEMM (out_proj, accumulate) ---------------------
template<int EPI>
__global__ __launch_bounds__(256) void k_sgemm_nt(
    const float* __restrict__ A, const float* __restrict__ Bm,
    float* __restrict__ C, int M, int N, int K)
{
    __shared__ float As[2][8][128];
    __shared__ float Bs[2][8][128];
    int tid = threadIdx.x;
    int mBase = blockIdx.y * 128, nBase = blockIdx.x * 128;

    int lr = tid >> 1;
    int lk = (tid & 1) * 4;
    const float* Ag = A + (size_t)(mBase + lr)*K + lk;
    const float* Bg = Bm + (size_t)(nBase + lr)*K + lk;

    int warp = tid >> 5, lane = tid & 31;
    int wm = warp & 1, wn = warp >> 1;
    int tm = lane & 7, tn = lane >> 3;
    int aoff = wm*64 + tm*4;
    int boff = wn*32 + tn*4;

    float acc[8][8];
    #pragma unroll
    for (int i = 0; i < 8; i++)
        #pragma unroll
        for (int j = 0; j < 8; j++) acc[i][j] = 0.f;

    float4 pa = *(const float4*)Ag;
    float4 pb = *(const float4*)Bg;
    As[0][lk+0][lr] = pa.x; As[0][lk+1][lr] = pa.y;
    As[0][lk+2][lr] = pa.z; As[0][lk+3][lr] = pa.w;
    Bs[0][lk+0][lr] = pb.x; Bs[0][lk+1][lr] = pb.y;
    Bs[0][lk+2][lr] = pb.z; Bs[0][lk+3][lr] = pb.w;
    __syncthreads();

    int buf = 0;
    for (int kb = 8; kb <= K; kb += 8) {
        if (kb < K) {
            pa = *(const float4*)(Ag + kb);
            pb = *(const float4*)(Bg + kb);
        }
        #pragma unroll
        for (int k = 0; k < 8; k++) {
            float a[8], b[8];
            *(float4*)(a)   = *(const float4*)&As[buf][k][aoff];
            *(float4*)(a+4) = *(const float4*)&As[buf][k][aoff+32];
            *(float4*)(b)   = *(const float4*)&Bs[buf][k][boff];
            *(float4*)(b+4) = *(const float4*)&Bs[buf][k][boff+16];
            #pragma unroll
            for (int i = 0; i < 8; i++)
                #pragma unroll
                for (int j = 0; j < 8; j++) acc[i][j] += a[i]*b[j];
        }
        if (kb < K) {
            buf ^= 1;
            As[buf][lk+0][lr] = pa.x; As[buf][lk+1][lr] = pa.y;
            As[buf][lk+2][lr] = pa.z; As[buf][lk+3][lr] = pa.w;
            Bs[buf][lk+0][lr] = pb.x; Bs[buf][lk+1][lr] = pb.y;
            Bs[buf][lk+2][lr] = pb.z; Bs[buf][lk+3][lr] = pb.w;
            __syncthreads();
        }
    }

    #pragma unroll
    for (int i = 0; i < 8; i++) {
        int mloc = wm*64 + ((i < 4) ? (tm*4 + i) : (32 + tm*4 + i - 4));
        float* Cp = C + (size_t)(mBase + mloc)*N + nBase;
        if (EPI == 0) {
            *(float4*)(Cp + boff)      = make_float4(acc[i][0],acc[i][1],acc[i][2],acc[i][3]);
            *(float4*)(Cp + boff + 16) = make_float4(acc[i][4],acc[i][5],acc[i][6],acc[i][7]);
        } else {
            float4 c0 = *(const float4*)(Cp + boff);
            float4 c1 = *(const float4*)(Cp + boff + 16);
            c0.x += acc[i][0]; c0.y += acc[i][1]; c0.z += acc[i][2]; c0.w += acc[i][3];
            c1.x += acc[i][4]; c1.y += acc[i][5]; c1.z += acc[i][6]; c1.w += acc[i][7];
            *(float4*)(Cp + boff)      = c0;
            *(float4*)(Cp + boff + 16) = c1;
        }
    }
}

// ------ kernel 4: FUSED conv+silu (+z-silu) + x_proj + dt_proj + softplus --------
__global__ __launch_bounds__(256) void k_convdbc(
    const float* __restrict__ cw, const float* __restrict__ cb,
    const float* __restrict__ xpw, const float* __restrict__ dtw,
    const float* __restrict__ dtb)
{
    __shared__ float xs[8][512];
    __shared__ float dbc_s[8][48];
    int r0 = blockIdx.x * 8;
    int tid = threadIdx.x;

    {
        int rg = tid >> 7;
        int d  = (tid & 127) * 4;
        size_t row0 = (size_t)r0 + rg*4;
        int t0 = (int)(row0 & (TT-1));

        float4 q0 = __ldg((const float4*)(cw + (d+0)*4));
        float4 q1 = __ldg((const float4*)(cw + (d+1)*4));
        float4 q2 = __ldg((const float4*)(cw + (d+2)*4));
        float4 q3 = __ldg((const float4*)(cw + (d+3)*4));
        float4 tap0 = make_float4(q0.x, q1.x, q2.x, q3.x);
        float4 tap1 = make_float4(q0.y, q1.y, q2.y, q3.y);
        float4 tap2 = make_float4(q0.z, q1.z, q2.z, q3.z);
        float4 tap3 = make_float4(q0.w, q1.w, q2.w, q3.w);
        float4 bias = __ldg((const float4*)(cb + d));

        const float* base = g_xz + row0*1024 + d;
        float4 xm3 = make_float4(0.f,0.f,0.f,0.f);
        float4 xm2 = xm3, xm1 = xm3;
        if (t0 > 0) {
            xm3 = __ldg((const float4*)(base - 3*1024));
            xm2 = __ldg((const float4*)(base - 2*1024));
            xm1 = __ldg((const float4*)(base - 1*1024));
        }
        float4 x0 = __ldg((const float4*)(base + 0*1024));
        float4 x1 = __ldg((const float4*)(base + 1*1024));
        float4 x2 = __ldg((const float4*)(base + 2*1024));
        float4 x3 = __ldg((const float4*)(base + 3*1024));

        float4 c0 = f4silu(f4fma(tap3, x0, f4fma(tap2, xm1, f4fma(tap1, xm2, f4fma(tap0, xm3, bias)))));
        float4 c1 = f4silu(f4fma(tap3, x1, f4fma(tap2, x0,  f4fma(tap1, xm1, f4fma(tap0, xm2, bias)))));
        float4 c2 = f4silu(f4fma(tap3, x2, f4fma(tap2, x1,  f4fma(tap1, x0,  f4fma(tap0, xm1, bias)))));
        float4 c3 = f4silu(f4fma(tap3, x3, f4fma(tap2, x2,  f4fma(tap1, x1,  f4fma(tap0, x0,  bias)))));

        int lr = rg*4;
        *(float4*)&xs[lr+0][d] = c0;
        *(float4*)&xs[lr+1][d] = c1;
        *(float4*)&xs[lr+2][d] = c2;
        *(float4*)&xs[lr+3][d] = c3;
        float* xcp = g_xc + row0*512 + d;
        *(float4*)(xcp + 0*512) = c0;
        *(float4*)(xcp + 1*512) = c1;
        *(float4*)(xcp + 2*512) = c2;
        *(float4*)(xcp + 3*512) = c3;

        const float* zbase = g_xz + row0*1024 + 512 + d;
        float* zsp = g_zs + row0*512 + d;
        #pragma unroll
        for (int j = 0; j < 4; j++) {
            float4 zv = __ldg((const float4*)(zbase + j*1024));
            *(float4*)(zsp + j*512) = f4silu(zv);
        }
    }
    __syncthreads();

    int w = tid >> 5, lane = tid & 31;
    const float4* wp = (const float4*)xpw;
    #pragma unroll
    for (int e0 = 0; e0 < 6; e0++) {
        int e = w*6 + e0;
        float4 wv0 = __ldg(&wp[e*128 + lane]);
        float4 wv1 = __ldg(&wp[e*128 + lane + 32]);
        float4 wv2 = __ldg(&wp[e*128 + lane + 64]);
        float4 wv3 = __ldg(&wp[e*128 + lane + 96]);
        #pragma unroll
        for (int r = 0; r < 8; r++) {
            const float4* xr = (const float4*)xs[r];
            float4 x0 = xr[lane], x1 = xr[lane+32], x2 = xr[lane+64], x3 = xr[lane+96];
            float s = x0.x*wv0.x + x0.y*wv0.y + x0.z*wv0.z + x0.w*wv0.w
                    + x1.x*wv1.x + x1.y*wv1.y + x1.z*wv1.z + x1.w*wv1.w
                    + x2.x*wv2.x + x2.y*wv2.y + x2.z*wv2.z + x2.w*wv2.w
                    + x3.x*wv3.x + x3.y*wv3.y + x3.z*wv3.z + x3.w*wv3.w;
            #pragma unroll
            for (int o = 16; o; o >>= 1) s += __shfl_xor_sync(0xffffffffu, s, o);
            if (lane == 0) {
                dbc_s[r][e] = s;
                g_dbc[(size_t)(r0 + r)*48 + e] = s;
            }
        }
    }
    __syncthreads();

    #pragma unroll
    for (int i = 0; i < 16; i++) {
        int idx = i*256 + tid;
        int r = idx >> 9;
        int d = idx & (DI-1);
        const float4* wr = (const float4*)(dtw + d*16);
        const float4* dr = (const float4*)dbc_s[r];
        float acc = dtb[d];
        #pragma unroll
        for (int c = 0; c < 4; c++) {
            float4 dv = dr[c];
            float4 wv = __ldg(&wr[c]);
            acc += dv.x*wv.x + dv.y*wv.y + dv.z*wv.z + dv.w*wv.w;
        }
        g_delta[(size_t)(r0 + r)*512 + d] = (acc > 20.f) ? acc : log1pf(__expf(acc));
    }
}

// -------- kernel 5a: scan pass A ----------
__global__ __launch_bounds__(256) void k_scanA(const float* __restrict__ A_log) {
    int gw = blockIdx.x*8 + (threadIdx.x >> 5);
    int lane = threadIdx.x & 31;
    int c = gw & (CHK-1);
    int dp = (gw >> 5) & 255;
    int b = gw >> 13;
    int half = lane >> 4, n = lane & 15;
    int d = dp*2 + half;
    float na = -__expf(A_log[d*16 + n]);
    float P = 1.f, S = 0.f;
    size_t row = (size_t)b*TT + c*CLEN;
    #pragma unroll 4
    for (int t = 0; t < CLEN; t++, row++) {
        float dl = __ldg(&g_delta[row*512 + d]);
        float xi = __ldg(&g_xc[row*512 + d]);
        float Bv = __ldg(&g_dbc[row*48 + 16 + n]);
        float da = __expf(dl * na);
        P *= da;
        S = da*S + (dl*xi)*Bv;
    }
    size_t o = (size_t)gw*32 + lane;
    g_P[o] = P;
    g_S[o] = S;
}

// -------- kernel 5b: scan pass B ----------
__global__ __launch_bounds__(256) void k_scanB() {
    int t = blockIdx.x*256 + threadIdx.x;
    int lane = t & 31;
    int wdp = t >> 5;
    float h = 0.f;
    #pragma unroll
    for (int c = 0; c < CHK; c++) {
        size_t o = ((size_t)wdp*CHK + c)*32 + lane;
        g_Hi[o] = h;
        h = g_P[o]*h + g_S[o];
    }
}

// -------- kernel 5c: scan pass C ----------
__global__ __launch_bounds__(256) void k_scanC(
    const float* __restrict__ A_log, const float* __restrict__ Dp)
{
    int gw = blockIdx.x*8 + (threadIdx.x >> 5);
    int lane = threadIdx.x & 31;
    int c = gw & (CHK-1);
    int dp = (gw >> 5) & 255;
    int b = gw >> 13;
    int half = lane >> 4, n = lane & 15;
    int d = dp*2 + half;
    float na = -__expf(A_log[d*16 + n]);
    float Dv = Dp[d];
    float h = g_Hi[(size_t)gw*32 + lane];
    size_t row = (size_t)b*TT + c*CLEN;
    #pragma unroll 4
    for (int t = 0; t < CLEN; t++, row++) {
        float dl = __ldg(&g_delta[row*512 + d]);
        float xi = __ldg(&g_xc[row*512 + d]);
        float Bv = __ldg(&g_dbc[row*48 + 16 + n]);
        float Cv = __ldg(&g_dbc[row*48 + 32 + n]);
        float da = __expf(dl * na);
        h = da*h + (dl*xi)*Bv;
        float v = h * Cv;
        #pragma unroll
        for (int o = 8; o; o >>= 1) v += __shfl_xor_sync(0xffffffffu, v, o);
        if (n == 0) {
            float y = v + Dv*xi;
            g_y[row*512 + d] = y * __ldg(&g_zs[row*512 + d]);
        }
    }
}

// ---------------- kernel 6: final rmsnorm + head + output ----------------
__global__ __launch_bounds__(256) void k_final(
    const float* __restrict__ fw, const float* __restrict__ hw,
    const float* __restrict__ hb, float* __restrict__ out)
{
    __shared__ float red[8];
    int row = blockIdx.x;
    int m = threadIdx.x;
    float v = g_h[row*DM + m];
    float ms = blockReduceSum256(v*v, red) * (1.f/256.f);
    float hn = v * rsqrtf(ms + EPS) * fw[m];
    float dot = blockReduceSum256(hn * hw[m], red);
    if (m == 0) {
        float dlt = dot + hb[0];
        out[row] = g_past[row] + dlt;
        out[BT + row] = dlt;
    }
}

// ---------------- host launcher ----------------
extern "C" void kernel_launch(void* const* d_in, const int* in_sizes, int n_in,
                              void* d_out, int out_size)
{
    const float* x    = (const float*)d_in[0];
    const float* ipw  = (const float*)d_in[1];
    const float* ipb  = (const float*)d_in[2];
    const float* lng  = (const float*)d_in[3];
    const float* lnb  = (const float*)d_in[4];
    const float* inpw = (const float*)d_in[5];   // (2,1024,256)
    const float* cw   = (const float*)d_in[6];
    const float* cb   = (const float*)d_in[7];
    const float* xpw  = (const float*)d_in[8];
    const float* dtw  = (const float*)d_in[9];
    const float* dtb  = (const float*)d_in[10];
    const float* alog = (const float*)d_in[11];
    const float* dpar = (const float*)d_in[12];
    const float* opw  = (const float*)d_in[13];  // (2,256,512)
    const float* rmsw = (const float*)d_in[14];
    const float* frw  = (const float*)d_in[15];
    const float* hw   = (const float*)d_in[16];
    const float* hb   = (const float*)d_in[17];
    float* out = (float*)d_out;

    float *pxz, *py, *ph;
    __nv_bfloat16 *puh, *pul, *pwh, *pwl;
    cudaGetSymbolAddress((void**)&pxz, g_xz);
    cudaGetSymbolAddress((void**)&py,  g_y);
    cudaGetSymbolAddress((void**)&ph,  g_h);
    cudaGetSymbolAddress((void**)&puh, g_uh);
    cudaGetSymbolAddress((void**)&pul, g_ul);
    cudaGetSymbolAddress((void**)&pwh, g_wh);
    cudaGetSymbolAddress((void**)&pwl, g_wl);

    // launch order: warm(1), cvtw(2), embed(3), mma_in(4 = ncu capture slot)
    k_warm<<<1, 32>>>();
    k_cvtw<<<(2*1024*DM)/256, 256>>>(inpw, pwh, pwl, 2*1024*DM);
    k_embed<<<BT, 256>>>(x, ipw, ipb, lng, lnb, rmsw);

    for (int l = 0; l < 2; l++) {
        if (l > 0) k_rms<<<BT, 256>>>(rmsw + l*DM);
        k_mma_in<<<dim3(8, BT/128), 256>>>(puh, pul,
            pwh + (size_t)l*1024*DM, pwl + (size_t)l*1024*DM, pxz, 1024);
        k_convdbc<<<BT/8, 256>>>(cw + l*DI*4, cb + l*DI, xpw + l*48*512, dtw + l*DI*16, dtb + l*DI);
        k_scanA<<<NWRP/8, 256>>>(alog + l*DI*16);
        k_scanB<<<256, 256>>>();
        k_scanC<<<NWRP/8, 256>>>(alog + l*DI*16, dpar + l*DI);
        k_sgemm_nt<1><<<dim3(256/128, BT/128), 256>>>(py, opw + (size_t)l*256*512, ph, BT, 256, 512);
    }

    k_final<<<BT, 256>>>(frw, hw, hb, out);
}